// round 1
// baseline (speedup 1.0000x reference)
#include <cuda_runtime.h>
#include <math.h>

#define NN 100000
#define NE 640000
#define H 128
#define H3 384
#define TT 3
#define PD 64
#define EMBD 96
#define SELD 32
#define GITERS 6
#define WPAD 132   // padded row stride (floats) for dot-form weight tiles

// ---------------- static device scratch (no dynamic allocation) ----------------
__device__ float g_h[NN * H];       // node state
__device__ float g_h0[NN * H];      // initial features
__device__ float g_agg[NN * H];     // aggregated messages (post mean + bias)
__device__ float g_buf[NN * H3];    // per-(node,type) scatter sums; reused as gh scratch
__device__ float g_gate[NE * H];    // per-edge gate
__device__ float g_cnt[NN * 4];     // [0..2] per-type in-counts, [3] 1/max(total,1)

// ---------------- setup kernels ----------------
__global__ void k_zero() {
    int stride = gridDim.x * blockDim.x;
    int tid = blockIdx.x * blockDim.x + threadIdx.x;
    for (int i = tid; i < NN * H3; i += stride) g_buf[i] = 0.f;
    for (int i = tid; i < NN * 4; i += stride) g_cnt[i] = 0.f;
}

__global__ void k_init(const int* __restrict__ xidx, const float* __restrict__ sel,
                       const float* __restrict__ emb) {
    int i = blockIdx.x * blockDim.x + threadIdx.x;
    if (i >= NN * H) return;
    int node = i >> 7, d = i & 127;
    float v = (d < EMBD) ? emb[xidx[node] * EMBD + d] : sel[node * SELD + d - EMBD];
    g_h0[i] = v;
    g_h[i] = v;
}

__global__ void k_counts(const int* __restrict__ eidx, const int* __restrict__ etype) {
    int e = blockIdx.x * blockDim.x + threadIdx.x;
    if (e < NE) atomicAdd(&g_cnt[eidx[NE + e] * 4 + etype[e]], 1.f);
}

__global__ void k_denom() {
    int n = blockIdx.x * blockDim.x + threadIdx.x;
    if (n < NN) {
        float c = g_cnt[n * 4] + g_cnt[n * 4 + 1] + g_cnt[n * 4 + 2];
        g_cnt[n * 4 + 3] = 1.f / fmaxf(c, 1.f);
    }
}

// gate[e][j] = 2*sigmoid( sum_k pos_enc[pos[e]][k] * Wg[k][j] + bg[j] )
// Wg is [PD, H] row-major -> direct smem copy, lane owns j4 = lane*4.
__global__ void k_gate(const int* __restrict__ epos, const float* __restrict__ pos_enc,
                       const float* __restrict__ Wg, const float* __restrict__ bg) {
    extern __shared__ float sm[];
    float* Wsm = sm;               // PD*H
    float* bgs = Wsm + PD * H;     // H
    float* stg = bgs + H;          // nwarps * 4 * PD
    for (int i = threadIdx.x; i < PD * H; i += blockDim.x) Wsm[i] = Wg[i];
    if (threadIdx.x < H) bgs[threadIdx.x] = bg[threadIdx.x];
    __syncthreads();

    int warp = threadIdx.x >> 5, lane = threadIdx.x & 31, nw = blockDim.x >> 5;
    float* xs = stg + warp * 4 * PD;
    for (int e0 = (blockIdx.x * nw + warp) * 4; e0 < NE; e0 += gridDim.x * nw * 4) {
        int ecnt = min(4, NE - e0);
        for (int i = lane; i < 4 * PD; i += 32) {
            int ee = e0 + (i >> 6);
            xs[i] = (ee < NE) ? pos_enc[epos[ee] * PD + (i & 63)] : 0.f;
        }
        __syncwarp();
        float acc[4][4] = {};
        #pragma unroll 4
        for (int k = 0; k < PD; k++) {
            float4 w = *(const float4*)&Wsm[k * H + lane * 4];
            #pragma unroll
            for (int n = 0; n < 4; n++) {
                float x = xs[n * PD + k];
                acc[n][0] += x * w.x; acc[n][1] += x * w.y;
                acc[n][2] += x * w.z; acc[n][3] += x * w.w;
            }
        }
        int j = lane * 4;
        float b0 = bgs[j], b1 = bgs[j + 1], b2v = bgs[j + 2], b3 = bgs[j + 3];
        for (int n = 0; n < ecnt; n++) {
            float4 o;
            o.x = 2.f / (1.f + expf(-(acc[n][0] + b0)));
            o.y = 2.f / (1.f + expf(-(acc[n][1] + b1)));
            o.z = 2.f / (1.f + expf(-(acc[n][2] + b2v)));
            o.w = 2.f / (1.f + expf(-(acc[n][3] + b3)));
            *(float4*)&g_gate[(e0 + n) * H + j] = o;
        }
        __syncwarp();
    }
}

// ---------------- per-iteration kernels ----------------
// scatter: buf[dst][type][:] += h[src] * gate[e]   (one warp per edge)
__global__ void k_scatter(const int* __restrict__ eidx, const int* __restrict__ etype) {
    int gwarp = (blockIdx.x * blockDim.x + threadIdx.x) >> 5;
    int lane = threadIdx.x & 31;
    int nwarps = (gridDim.x * blockDim.x) >> 5;
    for (int e = gwarp; e < NE; e += nwarps) {
        int src = __ldg(&eidx[e]);
        int dst = __ldg(&eidx[NE + e]);
        int t = __ldg(&etype[e]);
        float4 hv = *(const float4*)&g_h[src * H + lane * 4];
        float4 gv = *(const float4*)&g_gate[e * H + lane * 4];
        float* out = &g_buf[dst * H3 + t * H + lane * 4];
        atomicAdd(out + 0, hv.x * gv.x);
        atomicAdd(out + 1, hv.y * gv.y);
        atomicAdd(out + 2, hv.z * gv.z);
        atomicAdd(out + 3, hv.w * gv.w);
    }
}

// agg[d][j] = inv * ( sum_{tk} buf[d][tk] * Wt_flat[tk][j]  +  sum_t cnt_t*bt[t][j] )
// Wt flat is [384,128] row-major -> direct smem copy.
__global__ void k_agg(const float* __restrict__ Wt, const float* __restrict__ bt) {
    extern __shared__ float sm[];
    float* Wsm = sm;                   // TT*H*H
    float* bts = Wsm + TT * H * H;     // TT*H
    float* stg = bts + TT * H;         // nwarps * 2 * H3
    for (int i = threadIdx.x; i < TT * H * H; i += blockDim.x) Wsm[i] = Wt[i];
    for (int i = threadIdx.x; i < TT * H; i += blockDim.x) bts[i] = bt[i];
    __syncthreads();

    int warp = threadIdx.x >> 5, lane = threadIdx.x & 31, nw = blockDim.x >> 5;
    float* xs = stg + warp * 2 * H3;
    for (int d0 = (blockIdx.x * nw + warp) * 2; d0 < NN; d0 += gridDim.x * nw * 2) {
        int ncnt = min(2, NN - d0);
        for (int i = lane; i < 2 * H3; i += 32) {
            int dd = d0 + (i >= H3);
            xs[i] = (dd < NN) ? g_buf[dd * H3 + (i % H3)] : 0.f;
        }
        __syncwarp();
        float acc[2][4] = {};
        #pragma unroll 4
        for (int k = 0; k < H3; k++) {
            float4 w = *(const float4*)&Wsm[k * H + lane * 4];
            float x0 = xs[k], x1 = xs[H3 + k];
            acc[0][0] += x0 * w.x; acc[0][1] += x0 * w.y;
            acc[0][2] += x0 * w.z; acc[0][3] += x0 * w.w;
            acc[1][0] += x1 * w.x; acc[1][1] += x1 * w.y;
            acc[1][2] += x1 * w.z; acc[1][3] += x1 * w.w;
        }
        int j = lane * 4;
        for (int n = 0; n < ncnt; n++) {
            int d = d0 + n;
            float c0 = g_cnt[d * 4], c1 = g_cnt[d * 4 + 1], c2 = g_cnt[d * 4 + 2];
            float inv = g_cnt[d * 4 + 3];
            float4 o;
            o.x = (acc[n][0] + c0 * bts[j]     + c1 * bts[H + j]     + c2 * bts[2 * H + j])     * inv;
            o.y = (acc[n][1] + c0 * bts[j + 1] + c1 * bts[H + j + 1] + c2 * bts[2 * H + j + 1]) * inv;
            o.z = (acc[n][2] + c0 * bts[j + 2] + c1 * bts[H + j + 2] + c2 * bts[2 * H + j + 2]) * inv;
            o.w = (acc[n][3] + c0 * bts[j + 3] + c1 * bts[H + j + 3] + c2 * bts[2 * H + j + 3]) * inv;
            *(float4*)&g_agg[d * H + j] = o;
        }
        __syncwarp();
    }
}

// gh = h @ W_hh^T + b_hh  -> written into g_buf[d][g*H + j]
// W_hh is [384,128] (row = output). Dot-product form, rows padded to WPAD in smem.
__global__ void k_gh(const float* __restrict__ W_hh, const float* __restrict__ b_hh) {
    extern __shared__ float sm[];
    float* Wsm = sm;                   // H3*WPAD
    float* bs = Wsm + H3 * WPAD;       // H3
    float* stg = bs + H3;              // nwarps * 2 * H
    for (int i = threadIdx.x; i < H3 * H; i += blockDim.x)
        Wsm[(i >> 7) * WPAD + (i & 127)] = W_hh[i];
    for (int i = threadIdx.x; i < H3; i += blockDim.x) bs[i] = b_hh[i];
    __syncthreads();

    int warp = threadIdx.x >> 5, lane = threadIdx.x & 31, nw = blockDim.x >> 5;
    float* xs = stg + warp * 2 * H;
    for (int d0 = (blockIdx.x * nw + warp) * 2; d0 < NN; d0 += gridDim.x * nw * 2) {
        int ncnt = min(2, NN - d0);
        for (int i = lane; i < 2 * H; i += 32) {
            int dd = d0 + (i >> 7);
            xs[i] = (dd < NN) ? g_h[dd * H + (i & 127)] : 0.f;
        }
        __syncwarp();
        #pragma unroll
        for (int pass = 0; pass < 4; pass++) {
            int j = pass * 32 + lane;
            const float* w0p = &Wsm[(0 * H + j) * WPAD];
            const float* w1p = &Wsm[(1 * H + j) * WPAD];
            const float* w2p = &Wsm[(2 * H + j) * WPAD];
            float acc[2][3] = {};
            #pragma unroll 4
            for (int k4 = 0; k4 < 32; k4++) {
                float4 w0 = *(const float4*)&w0p[k4 * 4];
                float4 w1 = *(const float4*)&w1p[k4 * 4];
                float4 w2 = *(const float4*)&w2p[k4 * 4];
                float4 x0 = *(const float4*)&xs[k4 * 4];
                float4 x1 = *(const float4*)&xs[H + k4 * 4];
                acc[0][0] += x0.x * w0.x + x0.y * w0.y + x0.z * w0.z + x0.w * w0.w;
                acc[0][1] += x0.x * w1.x + x0.y * w1.y + x0.z * w1.z + x0.w * w1.w;
                acc[0][2] += x0.x * w2.x + x0.y * w2.y + x0.z * w2.z + x0.w * w2.w;
                acc[1][0] += x1.x * w0.x + x1.y * w0.y + x1.z * w0.z + x1.w * w0.w;
                acc[1][1] += x1.x * w1.x + x1.y * w1.y + x1.z * w1.z + x1.w * w1.w;
                acc[1][2] += x1.x * w2.x + x1.y * w2.y + x1.z * w2.z + x1.w * w2.w;
            }
            for (int n = 0; n < ncnt; n++) {
                int d = d0 + n;
                g_buf[d * H3 + 0 * H + j] = acc[n][0] + bs[0 * H + j];
                g_buf[d * H3 + 1 * H + j] = acc[n][1] + bs[1 * H + j];
                g_buf[d * H3 + 2 * H + j] = acc[n][2] + bs[2 * H + j];
            }
        }
        __syncwarp();
    }
}

// gi = agg @ W_ih^T + b_ih, then GRU combine with gh (in g_buf); zero g_buf after use.
__global__ void k_gru(const float* __restrict__ W_ih, const float* __restrict__ b_ih) {
    extern __shared__ float sm[];
    float* Wsm = sm;                   // H3*WPAD
    float* bs = Wsm + H3 * WPAD;       // H3
    float* stg = bs + H3;              // nwarps * 2 * H
    for (int i = threadIdx.x; i < H3 * H; i += blockDim.x)
        Wsm[(i >> 7) * WPAD + (i & 127)] = W_ih[i];
    for (int i = threadIdx.x; i < H3; i += blockDim.x) bs[i] = b_ih[i];
    __syncthreads();

    int warp = threadIdx.x >> 5, lane = threadIdx.x & 31, nw = blockDim.x >> 5;
    float* xs = stg + warp * 2 * H;
    for (int d0 = (blockIdx.x * nw + warp) * 2; d0 < NN; d0 += gridDim.x * nw * 2) {
        int ncnt = min(2, NN - d0);
        for (int i = lane; i < 2 * H; i += 32) {
            int dd = d0 + (i >> 7);
            xs[i] = (dd < NN) ? g_agg[dd * H + (i & 127)] : 0.f;
        }
        __syncwarp();
        #pragma unroll
        for (int pass = 0; pass < 4; pass++) {
            int j = pass * 32 + lane;
            const float* w0p = &Wsm[(0 * H + j) * WPAD];
            const float* w1p = &Wsm[(1 * H + j) * WPAD];
            const float* w2p = &Wsm[(2 * H + j) * WPAD];
            float acc[2][3] = {};
            #pragma unroll 4
            for (int k4 = 0; k4 < 32; k4++) {
                float4 w0 = *(const float4*)&w0p[k4 * 4];
                float4 w1 = *(const float4*)&w1p[k4 * 4];
                float4 w2 = *(const float4*)&w2p[k4 * 4];
                float4 x0 = *(const float4*)&xs[k4 * 4];
                float4 x1 = *(const float4*)&xs[H + k4 * 4];
                acc[0][0] += x0.x * w0.x + x0.y * w0.y + x0.z * w0.z + x0.w * w0.w;
                acc[0][1] += x0.x * w1.x + x0.y * w1.y + x0.z * w1.z + x0.w * w1.w;
                acc[0][2] += x0.x * w2.x + x0.y * w2.y + x0.z * w2.z + x0.w * w2.w;
                acc[1][0] += x1.x * w0.x + x1.y * w0.y + x1.z * w0.z + x1.w * w0.w;
                acc[1][1] += x1.x * w1.x + x1.y * w1.y + x1.z * w1.z + x1.w * w1.w;
                acc[1][2] += x1.x * w2.x + x1.y * w2.y + x1.z * w2.z + x1.w * w2.w;
            }
            for (int n = 0; n < ncnt; n++) {
                int d = d0 + n;
                float ghr = g_buf[d * H3 + j];
                float ghz = g_buf[d * H3 + H + j];
                float ghn = g_buf[d * H3 + 2 * H + j];
                float gir = acc[n][0] + bs[j];
                float giz = acc[n][1] + bs[H + j];
                float gin = acc[n][2] + bs[2 * H + j];
                float r = 1.f / (1.f + expf(-(gir + ghr)));
                float z = 1.f / (1.f + expf(-(giz + ghz)));
                float nn = tanhf(gin + r * ghn);
                float hold = g_h[d * H + j];
                g_h[d * H + j] = (1.f - z) * nn + z * hold;
                // re-zero scatter buffer for the next iteration
                g_buf[d * H3 + j] = 0.f;
                g_buf[d * H3 + H + j] = 0.f;
                g_buf[d * H3 + 2 * H + j] = 0.f;
            }
        }
        __syncwarp();
    }
}

// logits = relu([h, h0] @ W1 + b1) @ W2 + b2
__global__ void k_out(const float* __restrict__ W1, const float* __restrict__ b1,
                      const float* __restrict__ W2, const float* __restrict__ b2,
                      float* __restrict__ out) {
    extern __shared__ float sm[];
    float* Wsm = sm;                 // 2H * H
    float* b1s = Wsm + 2 * H * H;    // H
    float* W2s = b1s + H;            // H
    float* stg = W2s + H;            // nwarps * 2 * 2H
    for (int i = threadIdx.x; i < 2 * H * H; i += blockDim.x) Wsm[i] = W1[i];
    if (threadIdx.x < H) { b1s[threadIdx.x] = b1[threadIdx.x]; W2s[threadIdx.x] = W2[threadIdx.x]; }
    __syncthreads();
    float b2v = b2[0];

    int warp = threadIdx.x >> 5, lane = threadIdx.x & 31, nw = blockDim.x >> 5;
    float* xs = stg + warp * 2 * 2 * H;
    for (int d0 = (blockIdx.x * nw + warp) * 2; d0 < NN; d0 += gridDim.x * nw * 2) {
        int ncnt = min(2, NN - d0);
        for (int i = lane; i < 2 * 2 * H; i += 32) {
            int dd = d0 + (i >> 8);
            int k = i & 255;
            float v = 0.f;
            if (dd < NN) v = (k < H) ? g_h[dd * H + k] : g_h0[dd * H + k - H];
            xs[i] = v;
        }
        __syncwarp();
        float acc[2][4] = {};
        #pragma unroll 4
        for (int k = 0; k < 2 * H; k++) {
            float4 w = *(const float4*)&Wsm[k * H + lane * 4];
            float x0 = xs[k], x1 = xs[2 * H + k];
            acc[0][0] += x0 * w.x; acc[0][1] += x0 * w.y;
            acc[0][2] += x0 * w.z; acc[0][3] += x0 * w.w;
            acc[1][0] += x1 * w.x; acc[1][1] += x1 * w.y;
            acc[1][2] += x1 * w.z; acc[1][3] += x1 * w.w;
        }
        float4 wv2 = *(const float4*)&W2s[lane * 4];
        float4 bv = *(const float4*)&b1s[lane * 4];
        float p0, p1;
        p0 = fmaxf(acc[0][0] + bv.x, 0.f) * wv2.x + fmaxf(acc[0][1] + bv.y, 0.f) * wv2.y +
             fmaxf(acc[0][2] + bv.z, 0.f) * wv2.z + fmaxf(acc[0][3] + bv.w, 0.f) * wv2.w;
        p1 = fmaxf(acc[1][0] + bv.x, 0.f) * wv2.x + fmaxf(acc[1][1] + bv.y, 0.f) * wv2.y +
             fmaxf(acc[1][2] + bv.z, 0.f) * wv2.z + fmaxf(acc[1][3] + bv.w, 0.f) * wv2.w;
        #pragma unroll
        for (int o = 16; o > 0; o >>= 1) {
            p0 += __shfl_down_sync(0xffffffffu, p0, o);
            p1 += __shfl_down_sync(0xffffffffu, p1, o);
        }
        if (lane == 0) {
            if (ncnt > 0) out[d0] = p0 + b2v;
            if (ncnt > 1) out[d0 + 1] = p1 + b2v;
        }
        __syncwarp();
    }
}

// ---------------- launch ----------------
extern "C" void kernel_launch(void* const* d_in, const int* in_sizes, int n_in,
                              void* d_out, int out_size) {
    const int* xidx = (const int*)d_in[0];
    const float* sel = (const float*)d_in[1];
    const int* eidx = (const int*)d_in[2];
    const int* etype = (const int*)d_in[3];
    const int* epos = (const int*)d_in[4];
    const float* emb = (const float*)d_in[5];
    const float* pos_enc = (const float*)d_in[6];
    const float* Wg = (const float*)d_in[7];
    const float* bg = (const float*)d_in[8];
    const float* Wt = (const float*)d_in[9];
    const float* bt = (const float*)d_in[10];
    const float* W_ih = (const float*)d_in[11];
    const float* W_hh = (const float*)d_in[12];
    const float* b_ih = (const float*)d_in[13];
    const float* b_hh = (const float*)d_in[14];
    const float* W1 = (const float*)d_in[15];
    const float* b1 = (const float*)d_in[16];
    const float* W2 = (const float*)d_in[17];
    const float* b2 = (const float*)d_in[18];
    float* out = (float*)d_out;

    const int smem_gate = (PD * H + H + 8 * 4 * PD) * 4;           // 41472
    const int smem_agg  = (TT * H * H + TT * H + 8 * 2 * H3) * 4;  // 222720
    const int smem_gh   = (H3 * WPAD + H3 + 8 * 2 * H) * 4;        // 212480
    const int smem_out  = (2 * H * H + 2 * H + 8 * 2 * 2 * H) * 4; // 148480

    cudaFuncSetAttribute(k_agg, cudaFuncAttributeMaxDynamicSharedMemorySize, smem_agg);
    cudaFuncSetAttribute(k_gh,  cudaFuncAttributeMaxDynamicSharedMemorySize, smem_gh);
    cudaFuncSetAttribute(k_gru, cudaFuncAttributeMaxDynamicSharedMemorySize, smem_gh);
    cudaFuncSetAttribute(k_out, cudaFuncAttributeMaxDynamicSharedMemorySize, smem_out);

    k_zero<<<1024, 256>>>();
    k_init<<<(NN * H + 255) / 256, 256>>>(xidx, sel, emb);
    k_counts<<<(NE + 255) / 256, 256>>>(eidx, etype);
    k_denom<<<(NN + 255) / 256, 256>>>();
    k_gate<<<592, 256, smem_gate>>>(epos, pos_enc, Wg, bg);

    for (int it = 0; it < GITERS; it++) {
        k_scatter<<<2048, 256>>>(eidx, etype);
        k_agg<<<148, 256, smem_agg>>>(Wt, bt);
        k_gh<<<148, 256, smem_gh>>>(W_hh, b_hh);
        k_gru<<<148, 256, smem_gh>>>(W_ih, b_ih);
    }

    k_out<<<148, 256, smem_out>>>(W1, b1, W2, b2, out);
}

// round 4
// speedup vs baseline: 1.3415x; 1.3415x over previous
#include <cuda_runtime.h>
#include <math.h>

#define NN 100000
#define NE 640000
#define H 128
#define H3 384
#define TT 3
#define PD 64
#define EMBD 96
#define SELD 32
#define GITERS 6
#define WP 132   // row stride (floats): 16B-aligned rows AND conflict-free LDS.128
                 // (8-lane phase hits bank-quads (l*33)%8 = all distinct)

// ---------------- static device scratch ----------------
__device__ float g_h[NN * H];
__device__ float g_h0[NN * H];
__device__ float g_agg[NN * H];
__device__ float g_buf[NN * H3];    // msg sums, then reused as gh scratch
__device__ float g_gate[NE * H];    // gate in CSR-sorted edge order
__device__ float g_cnt[NN * 4];     // per-type in-counts + 1/max(total,1)
__device__ int   g_deg[NN];
__device__ int   g_cur[NN];
__device__ int   g_off[NN + 1];
__device__ int   g_srcs[NE];        // src per sorted edge
__device__ int   g_types[NE];       // type per sorted edge
__device__ int   g_eperm[NE];       // sorted pos -> original edge id

// ---------------- setup ----------------
__global__ void k_zero0() {
    int stride = gridDim.x * blockDim.x;
    int tid = blockIdx.x * blockDim.x + threadIdx.x;
    for (int i = tid; i < NN; i += stride) { g_deg[i] = 0; g_cur[i] = 0; }
    for (int i = tid; i < NN * 4; i += stride) g_cnt[i] = 0.f;
}

__global__ void k_init(const int* __restrict__ xidx, const float* __restrict__ sel,
                       const float* __restrict__ emb) {
    int i = blockIdx.x * blockDim.x + threadIdx.x;
    if (i >= NN * H) return;
    int node = i >> 7, d = i & 127;
    float v = (d < EMBD) ? emb[xidx[node] * EMBD + d] : sel[node * SELD + d - EMBD];
    g_h0[i] = v;
    g_h[i] = v;
}

__global__ void k_histo(const int* __restrict__ eidx, const int* __restrict__ etype) {
    int e = blockIdx.x * blockDim.x + threadIdx.x;
    if (e < NE) {
        int dst = eidx[NE + e];
        atomicAdd(&g_deg[dst], 1);
        atomicAdd(&g_cnt[dst * 4 + etype[e]], 1.f);   // +1.0 exact -> deterministic
    }
}

__global__ void k_scan() {                 // single block, 1024 threads
    __shared__ int sums[1024];
    int tid = threadIdx.x;
    const int chunk = (NN + 1023) / 1024;  // 98
    int base = tid * chunk;
    int hi = min(base + chunk, NN);
    int s = 0;
    for (int i = base; i < hi; i++) s += g_deg[i];
    sums[tid] = s;
    __syncthreads();
    for (int off = 1; off < 1024; off <<= 1) {
        int v = (tid >= off) ? sums[tid - off] : 0;
        __syncthreads();
        sums[tid] += v;
        __syncthreads();
    }
    int run = sums[tid] - s;               // exclusive prefix
    for (int i = base; i < hi; i++) { g_off[i] = run; run += g_deg[i]; }
    if (tid == 0) g_off[NN] = NE;
}

__global__ void k_fill(const int* __restrict__ eidx, const int* __restrict__ etype) {
    int e = blockIdx.x * blockDim.x + threadIdx.x;
    if (e < NE) {
        int dst = eidx[NE + e];
        int p = g_off[dst] + atomicAdd(&g_cur[dst], 1);
        g_srcs[p] = eidx[e];
        g_types[p] = etype[e];
        g_eperm[p] = e;
    }
}

__global__ void k_denom() {
    int n = blockIdx.x * blockDim.x + threadIdx.x;
    if (n < NN) {
        float c = g_cnt[n * 4] + g_cnt[n * 4 + 1] + g_cnt[n * 4 + 2];
        g_cnt[n * 4 + 3] = 1.f / fmaxf(c, 1.f);
    }
}

// gate[p][:] = 2*sigmoid(pos_enc[pos[eperm[p]]] @ Wg + bg), written in sorted order
__global__ __launch_bounds__(256, 1)
void k_gate(const int* __restrict__ epos, const float* __restrict__ pos_enc,
            const float* __restrict__ Wg, const float* __restrict__ bg) {
    extern __shared__ float sm[];
    float* Wsm = sm;               // PD*H
    float* bgs = Wsm + PD * H;     // H
    float* stg = bgs + H;          // 8 warps * 8 edges * PD
    for (int i = threadIdx.x; i < PD * H; i += blockDim.x) Wsm[i] = Wg[i];
    if (threadIdx.x < H) bgs[threadIdx.x] = bg[threadIdx.x];
    __syncthreads();

    int warp = threadIdx.x >> 5, lane = threadIdx.x & 31, nw = blockDim.x >> 5;
    float* xs = stg + warp * 8 * PD;
    for (int e0 = (blockIdx.x * nw + warp) * 8; e0 < NE; e0 += gridDim.x * nw * 8) {
        int ecnt = min(8, NE - e0);
        for (int i = lane; i < 8 * PD; i += 32) {
            int p = e0 + (i >> 6);
            xs[i] = (p < NE) ? pos_enc[epos[g_eperm[p]] * PD + (i & 63)] : 0.f;
        }
        __syncwarp();
        float acc[8][4] = {};
        const float* wb = Wsm + lane * 4;
        #pragma unroll 4
        for (int k4 = 0; k4 < PD / 4; k4++) {
            float4 w0 = *(const float4*)(wb + (k4 * 4 + 0) * H);
            float4 w1 = *(const float4*)(wb + (k4 * 4 + 1) * H);
            float4 w2 = *(const float4*)(wb + (k4 * 4 + 2) * H);
            float4 w3 = *(const float4*)(wb + (k4 * 4 + 3) * H);
            #pragma unroll
            for (int n = 0; n < 8; n++) {
                float4 x = *(const float4*)&xs[n * PD + k4 * 4];
                acc[n][0] += x.x * w0.x + x.y * w1.x + x.z * w2.x + x.w * w3.x;
                acc[n][1] += x.x * w0.y + x.y * w1.y + x.z * w2.y + x.w * w3.y;
                acc[n][2] += x.x * w0.z + x.y * w1.z + x.z * w2.z + x.w * w3.z;
                acc[n][3] += x.x * w0.w + x.y * w1.w + x.z * w2.w + x.w * w3.w;
            }
        }
        int j = lane * 4;
        float4 bv = *(const float4*)&bgs[j];
        for (int n = 0; n < ecnt; n++) {
            float4 o;
            o.x = 2.f / (1.f + expf(-(acc[n][0] + bv.x)));
            o.y = 2.f / (1.f + expf(-(acc[n][1] + bv.y)));
            o.z = 2.f / (1.f + expf(-(acc[n][2] + bv.z)));
            o.w = 2.f / (1.f + expf(-(acc[n][3] + bv.w)));
            *(float4*)&g_gate[(e0 + n) * H + j] = o;
        }
        __syncwarp();
    }
}

// ---------------- per-iteration ----------------
// gather: buf[n][t][:] = sum over in-edges of type t of h[src]*gate  (plain stores)
__global__ void k_gather() {
    int gwarp = (blockIdx.x * blockDim.x + threadIdx.x) >> 5;
    int lane = threadIdx.x & 31;
    int nwarps = (gridDim.x * blockDim.x) >> 5;
    int j = lane * 4;
    for (int n = gwarp; n < NN; n += nwarps) {
        int p0 = g_off[n], p1 = g_off[n + 1];
        float4 a0 = {0, 0, 0, 0}, a1 = {0, 0, 0, 0}, a2 = {0, 0, 0, 0};
        for (int p = p0; p < p1; p++) {
            int src = __ldg(&g_srcs[p]);       // warp-uniform
            int t = __ldg(&g_types[p]);        // warp-uniform
            float4 hv = *(const float4*)&g_h[src * H + j];
            float4 gv = *(const float4*)&g_gate[p * H + j];
            if (t == 0) {
                a0.x += hv.x * gv.x; a0.y += hv.y * gv.y; a0.z += hv.z * gv.z; a0.w += hv.w * gv.w;
            } else if (t == 1) {
                a1.x += hv.x * gv.x; a1.y += hv.y * gv.y; a1.z += hv.z * gv.z; a1.w += hv.w * gv.w;
            } else {
                a2.x += hv.x * gv.x; a2.y += hv.y * gv.y; a2.z += hv.z * gv.z; a2.w += hv.w * gv.w;
            }
        }
        *(float4*)&g_buf[n * H3 + 0 * H + j] = a0;
        *(float4*)&g_buf[n * H3 + 1 * H + j] = a1;
        *(float4*)&g_buf[n * H3 + 2 * H + j] = a2;
    }
}

// agg[d][:] = inv * ( sum_t buf[d][t] @ Wt[t]  + sum_t cnt_t*bt[t] )
__global__ __launch_bounds__(256, 1)
void k_agg(const float* __restrict__ Wt, const float* __restrict__ bt) {
    extern __shared__ float sm[];
    float* Wsm = sm;                   // TT*H*H = 49152 floats
    float* bts = Wsm + TT * H * H;     // TT*H
    float* stg = bts + TT * H;         // 8 warps * 6 * H
    for (int i = threadIdx.x; i < TT * H * H; i += blockDim.x) Wsm[i] = Wt[i];
    for (int i = threadIdx.x; i < TT * H; i += blockDim.x) bts[i] = bt[i];
    __syncthreads();

    int warp = threadIdx.x >> 5, lane = threadIdx.x & 31, nw = blockDim.x >> 5;
    float* xs = stg + warp * 6 * H;
    int j = lane * 4;
    for (int d0 = (blockIdx.x * nw + warp) * 6; d0 < NN; d0 += gridDim.x * nw * 6) {
        int ncnt = min(6, NN - d0);
        float acc[6][4] = {};
        #pragma unroll
        for (int t = 0; t < TT; t++) {
            __syncwarp();
            for (int i = lane; i < 6 * H; i += 32) {
                int dd = d0 + (i >> 7);
                xs[i] = (dd < NN) ? g_buf[dd * H3 + t * H + (i & 127)] : 0.f;
            }
            __syncwarp();
            const float* wb = Wsm + t * H * H + j;
            #pragma unroll 4
            for (int k4 = 0; k4 < H / 4; k4++) {
                float4 w0 = *(const float4*)(wb + (k4 * 4 + 0) * H);
                float4 w1 = *(const float4*)(wb + (k4 * 4 + 1) * H);
                float4 w2 = *(const float4*)(wb + (k4 * 4 + 2) * H);
                float4 w3 = *(const float4*)(wb + (k4 * 4 + 3) * H);
                #pragma unroll
                for (int n = 0; n < 6; n++) {
                    float4 x = *(const float4*)&xs[n * H + k4 * 4];
                    acc[n][0] += x.x * w0.x + x.y * w1.x + x.z * w2.x + x.w * w3.x;
                    acc[n][1] += x.x * w0.y + x.y * w1.y + x.z * w2.y + x.w * w3.y;
                    acc[n][2] += x.x * w0.z + x.y * w1.z + x.z * w2.z + x.w * w3.z;
                    acc[n][3] += x.x * w0.w + x.y * w1.w + x.z * w2.w + x.w * w3.w;
                }
            }
        }
        for (int n = 0; n < ncnt; n++) {
            int d = d0 + n;
            float c0 = g_cnt[d * 4], c1 = g_cnt[d * 4 + 1], c2 = g_cnt[d * 4 + 2];
            float inv = g_cnt[d * 4 + 3];
            float4 b0 = *(const float4*)&bts[j];
            float4 b1 = *(const float4*)&bts[H + j];
            float4 b2v = *(const float4*)&bts[2 * H + j];
            float4 o;
            o.x = (acc[n][0] + c0 * b0.x + c1 * b1.x + c2 * b2v.x) * inv;
            o.y = (acc[n][1] + c0 * b0.y + c1 * b1.y + c2 * b2v.y) * inv;
            o.z = (acc[n][2] + c0 * b0.z + c1 * b1.z + c2 * b2v.z) * inv;
            o.w = (acc[n][3] + c0 * b0.w + c1 * b1.w + c2 * b2v.w) * inv;
            *(float4*)&g_agg[d * H + j] = o;
        }
        __syncwarp();
    }
}

// gh = h @ W_hh^T + b_hh  (dot form, WP=132: aligned + conflict-free), -> g_buf
__global__ __launch_bounds__(256, 1)
void k_gh(const float* __restrict__ W_hh, const float* __restrict__ b_hh) {
    extern __shared__ float sm[];
    float* Wsm = sm;                   // H3*WP
    float* bs = Wsm + H3 * WP;
    float* stg = bs + H3;              // 8 warps * 6 * H
    for (int i = threadIdx.x; i < H3 * H; i += blockDim.x)
        Wsm[(i >> 7) * WP + (i & 127)] = W_hh[i];
    for (int i = threadIdx.x; i < H3; i += blockDim.x) bs[i] = b_hh[i];
    __syncthreads();

    int warp = threadIdx.x >> 5, lane = threadIdx.x & 31, nw = blockDim.x >> 5;
    float* xs = stg + warp * 6 * H;
    for (int d0 = (blockIdx.x * nw + warp) * 6; d0 < NN; d0 += gridDim.x * nw * 6) {
        int ncnt = min(6, NN - d0);
        for (int i = lane; i < 6 * H; i += 32) {
            int dd = d0 + (i >> 7);
            xs[i] = (dd < NN) ? g_h[dd * H + (i & 127)] : 0.f;
        }
        __syncwarp();
        #pragma unroll
        for (int pass = 0; pass < 4; pass++) {
            int j = pass * 32 + lane;
            const float* w0p = Wsm + (0 * H + j) * WP;
            const float* w1p = Wsm + (1 * H + j) * WP;
            const float* w2p = Wsm + (2 * H + j) * WP;
            float acc[6][3] = {};
            #pragma unroll 4
            for (int k4 = 0; k4 < H / 4; k4++) {
                float4 w0 = *(const float4*)(w0p + k4 * 4);
                float4 w1 = *(const float4*)(w1p + k4 * 4);
                float4 w2 = *(const float4*)(w2p + k4 * 4);
                #pragma unroll
                for (int n = 0; n < 6; n++) {
                    float4 x = *(const float4*)&xs[n * H + k4 * 4];
                    acc[n][0] += x.x * w0.x + x.y * w0.y + x.z * w0.z + x.w * w0.w;
                    acc[n][1] += x.x * w1.x + x.y * w1.y + x.z * w1.z + x.w * w1.w;
                    acc[n][2] += x.x * w2.x + x.y * w2.y + x.z * w2.z + x.w * w2.w;
                }
            }
            for (int n = 0; n < ncnt; n++) {
                int d = d0 + n;
                g_buf[d * H3 + 0 * H + j] = acc[n][0] + bs[0 * H + j];
                g_buf[d * H3 + 1 * H + j] = acc[n][1] + bs[1 * H + j];
                g_buf[d * H3 + 2 * H + j] = acc[n][2] + bs[2 * H + j];
            }
        }
        __syncwarp();
    }
}

// gi = agg @ W_ih^T + b_ih, fused with GRU combine (gh in g_buf)
__global__ __launch_bounds__(256, 1)
void k_gru(const float* __restrict__ W_ih, const float* __restrict__ b_ih) {
    extern __shared__ float sm[];
    float* Wsm = sm;
    float* bs = Wsm + H3 * WP;
    float* stg = bs + H3;
    for (int i = threadIdx.x; i < H3 * H; i += blockDim.x)
        Wsm[(i >> 7) * WP + (i & 127)] = W_ih[i];
    for (int i = threadIdx.x; i < H3; i += blockDim.x) bs[i] = b_ih[i];
    __syncthreads();

    int warp = threadIdx.x >> 5, lane = threadIdx.x & 31, nw = blockDim.x >> 5;
    float* xs = stg + warp * 6 * H;
    for (int d0 = (blockIdx.x * nw + warp) * 6; d0 < NN; d0 += gridDim.x * nw * 6) {
        int ncnt = min(6, NN - d0);
        for (int i = lane; i < 6 * H; i += 32) {
            int dd = d0 + (i >> 7);
            xs[i] = (dd < NN) ? g_agg[dd * H + (i & 127)] : 0.f;
        }
        __syncwarp();
        #pragma unroll
        for (int pass = 0; pass < 4; pass++) {
            int j = pass * 32 + lane;
            const float* w0p = Wsm + (0 * H + j) * WP;
            const float* w1p = Wsm + (1 * H + j) * WP;
            const float* w2p = Wsm + (2 * H + j) * WP;
            float acc[6][3] = {};
            #pragma unroll 4
            for (int k4 = 0; k4 < H / 4; k4++) {
                float4 w0 = *(const float4*)(w0p + k4 * 4);
                float4 w1 = *(const float4*)(w1p + k4 * 4);
                float4 w2 = *(const float4*)(w2p + k4 * 4);
                #pragma unroll
                for (int n = 0; n < 6; n++) {
                    float4 x = *(const float4*)&xs[n * H + k4 * 4];
                    acc[n][0] += x.x * w0.x + x.y * w0.y + x.z * w0.z + x.w * w0.w;
                    acc[n][1] += x.x * w1.x + x.y * w1.y + x.z * w1.z + x.w * w1.w;
                    acc[n][2] += x.x * w2.x + x.y * w2.y + x.z * w2.z + x.w * w2.w;
                }
            }
            for (int n = 0; n < ncnt; n++) {
                int d = d0 + n;
                float ghr = g_buf[d * H3 + j];
                float ghz = g_buf[d * H3 + H + j];
                float ghn = g_buf[d * H3 + 2 * H + j];
                float r = 1.f / (1.f + expf(-(acc[n][0] + bs[j] + ghr)));
                float z = 1.f / (1.f + expf(-(acc[n][1] + bs[H + j] + ghz)));
                float nn = tanhf(acc[n][2] + bs[2 * H + j] + r * ghn);
                float hold = g_h[d * H + j];
                g_h[d * H + j] = (1.f - z) * nn + z * hold;
            }
        }
        __syncwarp();
    }
}

// logits = relu([h, h0] @ W1 + b1) @ W2 + b2
__global__ __launch_bounds__(256, 1)
void k_out(const float* __restrict__ W1, const float* __restrict__ b1,
           const float* __restrict__ W2, const float* __restrict__ b2,
           float* __restrict__ out) {
    extern __shared__ float sm[];
    float* Wsm = sm;                 // 2H*H
    float* b1s = Wsm + 2 * H * H;
    float* W2s = b1s + H;
    float* stg = W2s + H;            // 8 warps * 6 * 2H
    for (int i = threadIdx.x; i < 2 * H * H; i += blockDim.x) Wsm[i] = W1[i];
    if (threadIdx.x < H) { b1s[threadIdx.x] = b1[threadIdx.x]; W2s[threadIdx.x] = W2[threadIdx.x]; }
    __syncthreads();
    float b2v = b2[0];

    int warp = threadIdx.x >> 5, lane = threadIdx.x & 31, nw = blockDim.x >> 5;
    float* xs = stg + warp * 6 * 2 * H;
    int j = lane * 4;
    for (int d0 = (blockIdx.x * nw + warp) * 6; d0 < NN; d0 += gridDim.x * nw * 6) {
        int ncnt = min(6, NN - d0);
        for (int i = lane; i < 6 * 2 * H; i += 32) {
            int dd = d0 + (i >> 8);
            int k = i & 255;
            float v = 0.f;
            if (dd < NN) v = (k < H) ? g_h[dd * H + k] : g_h0[dd * H + k - H];
            xs[i] = v;
        }
        __syncwarp();
        float acc[6][4] = {};
        const float* wb = Wsm + j;
        #pragma unroll 4
        for (int k4 = 0; k4 < 2 * H / 4; k4++) {
            float4 w0 = *(const float4*)(wb + (k4 * 4 + 0) * H);
            float4 w1 = *(const float4*)(wb + (k4 * 4 + 1) * H);
            float4 w2 = *(const float4*)(wb + (k4 * 4 + 2) * H);
            float4 w3 = *(const float4*)(wb + (k4 * 4 + 3) * H);
            #pragma unroll
            for (int n = 0; n < 6; n++) {
                float4 x = *(const float4*)&xs[n * 2 * H + k4 * 4];
                acc[n][0] += x.x * w0.x + x.y * w1.x + x.z * w2.x + x.w * w3.x;
                acc[n][1] += x.x * w0.y + x.y * w1.y + x.z * w2.y + x.w * w3.y;
                acc[n][2] += x.x * w0.z + x.y * w1.z + x.z * w2.z + x.w * w3.z;
                acc[n][3] += x.x * w0.w + x.y * w1.w + x.z * w2.w + x.w * w3.w;
            }
        }
        float4 wv2 = *(const float4*)&W2s[j];
        float4 bv = *(const float4*)&b1s[j];
        float p[6];
        #pragma unroll
        for (int n = 0; n < 6; n++) {
            p[n] = fmaxf(acc[n][0] + bv.x, 0.f) * wv2.x + fmaxf(acc[n][1] + bv.y, 0.f) * wv2.y +
                   fmaxf(acc[n][2] + bv.z, 0.f) * wv2.z + fmaxf(acc[n][3] + bv.w, 0.f) * wv2.w;
        }
        #pragma unroll
        for (int o = 16; o > 0; o >>= 1) {
            #pragma unroll
            for (int n = 0; n < 6; n++) p[n] += __shfl_down_sync(0xffffffffu, p[n], o);
        }
        if (lane == 0) {
            for (int n = 0; n < ncnt; n++) out[d0 + n] = p[n] + b2v;
        }
        __syncwarp();
    }
}

// ---------------- launch ----------------
extern "C" void kernel_launch(void* const* d_in, const int* in_sizes, int n_in,
                              void* d_out, int out_size) {
    const int* xidx = (const int*)d_in[0];
    const float* sel = (const float*)d_in[1];
    const int* eidx = (const int*)d_in[2];
    const int* etype = (const int*)d_in[3];
    const int* epos = (const int*)d_in[4];
    const float* emb = (const float*)d_in[5];
    const float* pos_enc = (const float*)d_in[6];
    const float* Wg = (const float*)d_in[7];
    const float* bg = (const float*)d_in[8];
    const float* Wt = (const float*)d_in[9];
    const float* bt = (const float*)d_in[10];
    const float* W_ih = (const float*)d_in[11];
    const float* W_hh = (const float*)d_in[12];
    const float* b_ih = (const float*)d_in[13];
    const float* b_hh = (const float*)d_in[14];
    const float* W1 = (const float*)d_in[15];
    const float* b1 = (const float*)d_in[16];
    const float* W2 = (const float*)d_in[17];
    const float* b2 = (const float*)d_in[18];
    float* out = (float*)d_out;

    const int smem_gate = (PD * H + H + 8 * 8 * PD) * 4;            // 49664
    const int smem_agg  = (TT * H * H + TT * H + 8 * 6 * H) * 4;    // 222720
    const int smem_gh   = (H3 * WP + H3 + 8 * 6 * H) * 4;           // 228864
    const int smem_out  = (2 * H * H + 2 * H + 8 * 6 * 2 * H) * 4;  // 181248

    static int attr_done = 0;
    if (!attr_done) {
        cudaFuncSetAttribute(k_gate, cudaFuncAttributeMaxDynamicSharedMemorySize, smem_gate);
        cudaFuncSetAttribute(k_agg, cudaFuncAttributeMaxDynamicSharedMemorySize, smem_agg);
        cudaFuncSetAttribute(k_gh,  cudaFuncAttributeMaxDynamicSharedMemorySize, smem_gh);
        cudaFuncSetAttribute(k_gru, cudaFuncAttributeMaxDynamicSharedMemorySize, smem_gh);
        cudaFuncSetAttribute(k_out, cudaFuncAttributeMaxDynamicSharedMemorySize, smem_out);
        attr_done = 1;
    }

    k_zero0<<<512, 256>>>();
    k_init<<<(NN * H + 255) / 256, 256>>>(xidx, sel, emb);
    k_histo<<<(NE + 255) / 256, 256>>>(eidx, etype);
    k_scan<<<1, 1024>>>();
    k_fill<<<(NE + 255) / 256, 256>>>(eidx, etype);
    k_denom<<<(NN + 255) / 256, 256>>>();
    k_gate<<<592, 256, smem_gate>>>(epos, pos_enc, Wg, bg);

    for (int it = 0; it < GITERS; it++) {
        k_gather<<<2048, 256>>>();
        k_agg<<<148, 256, smem_agg>>>(Wt, bt);
        k_gh<<<148, 256, smem_gh>>>(W_hh, b_hh);
        k_gru<<<148, 256, smem_gh>>>(W_ih, b_ih);
    }

    k_out<<<148, 256, smem_out>>>(W1, b1, W2, b2, out);
}

// round 13
// speedup vs baseline: 2.0136x; 1.5009x over previous
#include <cuda_runtime.h>
#include <math.h>

#define NN 100000
#define NE 640000
#define H 128
#define H3 384
#define TT 3
#define PD 64
#define EMBD 96
#define SELD 32
#define GITERS 6
#define WTR 388   // transposed-weight row stride (floats): 16B-aligned, conflict-free
#define XST 10    // x staging stride (floats): 8B-aligned pairs, <=2-way STS conflict

typedef unsigned long long ull;

// ---------------- f32x2 helpers ----------------
__device__ __forceinline__ void fma2(ull& d, ull a, ull b) {
    asm("fma.rn.f32x2 %0, %1, %2, %0;" : "+l"(d) : "l"(a), "l"(b));
}
__device__ __forceinline__ ull pack2(float lo, float hi) {
    ull r; asm("mov.b64 %0, {%1, %2};" : "=l"(r) : "f"(lo), "f"(hi)); return r;
}
__device__ __forceinline__ float2 unpack2(ull v) {
    float2 r; asm("mov.b64 {%0, %1}, %2;" : "=f"(r.x), "=f"(r.y) : "l"(v)); return r;
}

// ---------------- static device scratch ----------------
__device__ float g_h[NN * H];
__device__ float g_h0[NN * H];
__device__ float g_agg[NN * H];
__device__ float g_buf[NN * H3];    // msg sums, then reused as gh scratch
__device__ float g_gate[NE * H];    // gate in CSR-sorted edge order
__device__ float g_cnt[NN * 4];     // per-type in-counts + 1/max(total,1)
__device__ int   g_deg[NN];
__device__ int   g_cur[NN];
__device__ int   g_off[NN + 1];
__device__ int   g_srcs[NE];
__device__ int   g_types[NE];
__device__ int   g_eperm[NE];
__device__ int   g_bsum[128];
__device__ int   g_bpre[128];

#define SCAN_B 1024
#define SCAN_NB 98   // ceil(100000/1024)

// ---------------- setup ----------------
__global__ void k_zero0() {
    int stride = gridDim.x * blockDim.x;
    int tid = blockIdx.x * blockDim.x + threadIdx.x;
    for (int i = tid; i < NN; i += stride) { g_deg[i] = 0; g_cur[i] = 0; }
    for (int i = tid; i < NN * 4; i += stride) g_cnt[i] = 0.f;
}

__global__ void k_init(const int* __restrict__ xidx, const float* __restrict__ sel,
                       const float* __restrict__ emb) {
    int i = blockIdx.x * blockDim.x + threadIdx.x;
    if (i >= NN * H) return;
    int node = i >> 7, d = i & 127;
    float v = (d < EMBD) ? emb[xidx[node] * EMBD + d] : sel[node * SELD + d - EMBD];
    g_h0[i] = v;
    g_h[i] = v;
}

__global__ void k_histo(const int* __restrict__ eidx, const int* __restrict__ etype) {
    int e = blockIdx.x * blockDim.x + threadIdx.x;
    if (e < NE) {
        int dst = eidx[NE + e];
        atomicAdd(&g_deg[dst], 1);
        atomicAdd(&g_cnt[dst * 4 + etype[e]], 1.f);
    }
}

// coalesced 3-phase scan of g_deg -> g_off
__global__ void k_scan1() {
    __shared__ int wsum[8];
    int base = blockIdx.x * SCAN_B;
    int s = 0;
    for (int i = threadIdx.x; i < SCAN_B; i += blockDim.x) {
        int idx = base + i;
        s += (idx < NN) ? g_deg[idx] : 0;
    }
    for (int o = 16; o > 0; o >>= 1) s += __shfl_down_sync(0xffffffffu, s, o);
    int lane = threadIdx.x & 31, wid = threadIdx.x >> 5;
    if (lane == 0) wsum[wid] = s;
    __syncthreads();
    if (threadIdx.x == 0) {
        int t = 0;
        for (int w = 0; w < (int)(blockDim.x >> 5); w++) t += wsum[w];
        g_bsum[blockIdx.x] = t;
    }
}
__global__ void k_scan2() {
    if (threadIdx.x == 0) {
        int run = 0;
        for (int b = 0; b < SCAN_NB; b++) { g_bpre[b] = run; run += g_bsum[b]; }
        g_off[NN] = NE;
    }
}
__global__ void k_scan3() {
    __shared__ int wsum[32];
    int i = blockIdx.x * SCAN_B + threadIdx.x;
    int lane = threadIdx.x & 31, wid = threadIdx.x >> 5;
    int x = (i < NN) ? g_deg[i] : 0;
    int incl = x;
    for (int o = 1; o < 32; o <<= 1) {
        int v = __shfl_up_sync(0xffffffffu, incl, o);
        if (lane >= o) incl += v;
    }
    if (lane == 31) wsum[wid] = incl;
    __syncthreads();
    if (wid == 0) {
        int s = wsum[lane];
        for (int o = 1; o < 32; o <<= 1) {
            int v = __shfl_up_sync(0xffffffffu, s, o);
            if (lane >= o) s += v;
        }
        wsum[lane] = s;
    }
    __syncthreads();
    int excl = incl - x + (wid > 0 ? wsum[wid - 1] : 0);
    if (i < NN) g_off[i] = g_bpre[blockIdx.x] + excl;
}

__global__ void k_fill(const int* __restrict__ eidx, const int* __restrict__ etype) {
    int e = blockIdx.x * blockDim.x + threadIdx.x;
    if (e < NE) {
        int dst = eidx[NE + e];
        int p = g_off[dst] + atomicAdd(&g_cur[dst], 1);
        g_srcs[p] = eidx[e];
        g_types[p] = etype[e];
        g_eperm[p] = e;
    }
}

__global__ void k_denom() {
    int n = blockIdx.x * blockDim.x + threadIdx.x;
    if (n < NN) {
        float c = g_cnt[n * 4] + g_cnt[n * 4 + 1] + g_cnt[n * 4 + 2];
        g_cnt[n * 4 + 3] = 1.f / fmaxf(c, 1.f);
    }
}

// gate[p][:] = 2*sigmoid(pos_enc[pos[eperm[p]]] @ Wg + bg)  — f32x2 node-pair GEMM
__global__ __launch_bounds__(256, 1)
void k_gate(const int* __restrict__ epos, const float* __restrict__ pos_enc,
            const float* __restrict__ Wg, const float* __restrict__ bg) {
    extern __shared__ float sm[];
    float* Wsm = sm;                // PD*H = 8192
    float* bgs = Wsm + PD * H;      // 128
    float* stg = bgs + H;           // 8 warps * 64*XST
    for (int i = threadIdx.x; i < PD * H; i += blockDim.x) Wsm[i] = Wg[i];
    if (threadIdx.x < H) bgs[threadIdx.x] = bg[threadIdx.x];
    __syncthreads();

    int warp = threadIdx.x >> 5, lane = threadIdx.x & 31;
    float* xs = stg + warp * PD * XST;
    int j4 = lane * 4;
    for (int e0 = (blockIdx.x * 8 + warp) * 8; e0 < NE; e0 += gridDim.x * 64) {
        __syncwarp();
        #pragma unroll
        for (int it = 0; it < 16; it++) {
            int idx = it * 32 + lane;
            int n = idx >> 6, kk = idx & 63;
            int p = e0 + n;
            xs[kk * XST + n] = (p < NE) ? pos_enc[epos[g_eperm[p]] * PD + kk] : 0.f;
        }
        __syncwarp();
        ull acc[4][4];
        #pragma unroll
        for (int m = 0; m < 4; m++)
            #pragma unroll
            for (int o = 0; o < 4; o++) acc[m][o] = 0ull;
        #pragma unroll 4
        for (int kk = 0; kk < PD; kk++) {
            float4 w = *(const float4*)(Wsm + kk * H + j4);
            ull w0 = pack2(w.x, w.x), w1 = pack2(w.y, w.y);
            ull w2 = pack2(w.z, w.z), w3 = pack2(w.w, w.w);
            #pragma unroll
            for (int m = 0; m < 4; m++) {
                ull xp = *(const ull*)(xs + kk * XST + 2 * m);
                fma2(acc[m][0], w0, xp);
                fma2(acc[m][1], w1, xp);
                fma2(acc[m][2], w2, xp);
                fma2(acc[m][3], w3, xp);
            }
        }
        float4 bv = *(const float4*)&bgs[j4];
        #pragma unroll
        for (int m = 0; m < 4; m++) {
            float2 u0 = unpack2(acc[m][0]), u1 = unpack2(acc[m][1]);
            float2 u2 = unpack2(acc[m][2]), u3 = unpack2(acc[m][3]);
            #pragma unroll
            for (int par = 0; par < 2; par++) {
                int e = e0 + 2 * m + par;
                if (e < NE) {
                    float4 o;
                    o.x = 2.f / (1.f + expf(-((par ? u0.y : u0.x) + bv.x)));
                    o.y = 2.f / (1.f + expf(-((par ? u1.y : u1.x) + bv.y)));
                    o.z = 2.f / (1.f + expf(-((par ? u2.y : u2.x) + bv.z)));
                    o.w = 2.f / (1.f + expf(-((par ? u3.y : u3.x) + bv.w)));
                    *(float4*)&g_gate[e * H + j4] = o;
                }
            }
        }
        __syncwarp();
    }
}

// ---------------- per-iteration ----------------
__global__ void k_gather() {
    int gwarp = (blockIdx.x * blockDim.x + threadIdx.x) >> 5;
    int lane = threadIdx.x & 31;
    int nwarps = (gridDim.x * blockDim.x) >> 5;
    int j = lane * 4;
    for (int n = gwarp; n < NN; n += nwarps) {
        int p0 = g_off[n], p1 = g_off[n + 1];
        float4 a0 = {0, 0, 0, 0}, a1 = {0, 0, 0, 0}, a2 = {0, 0, 0, 0};
        for (int p = p0; p < p1; p++) {
            int src = __ldg(&g_srcs[p]);
            int t = __ldg(&g_types[p]);
            float4 hv = *(const float4*)&g_h[src * H + j];
            float4 gv = *(const float4*)&g_gate[p * H + j];
            if (t == 0) {
                a0.x += hv.x * gv.x; a0.y += hv.y * gv.y; a0.z += hv.z * gv.z; a0.w += hv.w * gv.w;
            } else if (t == 1) {
                a1.x += hv.x * gv.x; a1.y += hv.y * gv.y; a1.z += hv.z * gv.z; a1.w += hv.w * gv.w;
            } else {
                a2.x += hv.x * gv.x; a2.y += hv.y * gv.y; a2.z += hv.z * gv.z; a2.w += hv.w * gv.w;
            }
        }
        *(float4*)&g_buf[n * H3 + 0 * H + j] = a0;
        *(float4*)&g_buf[n * H3 + 1 * H + j] = a1;
        *(float4*)&g_buf[n * H3 + 2 * H + j] = a2;
    }
}

// agg[d][:] = inv * ( sum_tk buf[d][tk] * Wt[tk][:] + sum_t cnt_t*bt[t][:] )
__global__ __launch_bounds__(256, 1)
void k_agg(const float* __restrict__ Wt, const float* __restrict__ bt) {
    extern __shared__ float sm[];
    float* Wsm = sm;                   // 384*128
    float* bts = Wsm + H3 * H;         // 384
    float* stg = bts + H3;             // 8 * 32*XST
    for (int i = threadIdx.x; i < H3 * H; i += blockDim.x) Wsm[i] = Wt[i];
    for (int i = threadIdx.x; i < H3; i += blockDim.x) bts[i] = bt[i];
    __syncthreads();

    int warp = threadIdx.x >> 5, lane = threadIdx.x & 31;
    float* xs = stg + warp * 32 * XST;
    int j4 = lane * 4;
    for (int d0 = (blockIdx.x * 8 + warp) * 8; d0 < NN; d0 += gridDim.x * 64) {
        ull acc[4][4];
        #pragma unroll
        for (int m = 0; m < 4; m++)
            #pragma unroll
            for (int o = 0; o < 4; o++) acc[m][o] = 0ull;
        for (int kc = 0; kc < H3; kc += 32) {
            __syncwarp();
            #pragma unroll
            for (int n = 0; n < 8; n++) {
                int d = d0 + n;
                xs[lane * XST + n] = (d < NN) ? g_buf[d * H3 + kc + lane] : 0.f;
            }
            __syncwarp();
            #pragma unroll 4
            for (int kk = 0; kk < 32; kk++) {
                float4 w = *(const float4*)(Wsm + (kc + kk) * H + j4);
                ull w0 = pack2(w.x, w.x), w1 = pack2(w.y, w.y);
                ull w2 = pack2(w.z, w.z), w3 = pack2(w.w, w.w);
                #pragma unroll
                for (int m = 0; m < 4; m++) {
                    ull xp = *(const ull*)(xs + kk * XST + 2 * m);
                    fma2(acc[m][0], w0, xp);
                    fma2(acc[m][1], w1, xp);
                    fma2(acc[m][2], w2, xp);
                    fma2(acc[m][3], w3, xp);
                }
            }
        }
        float4 b0 = *(const float4*)&bts[j4];
        float4 b1 = *(const float4*)&bts[H + j4];
        float4 b2v = *(const float4*)&bts[2 * H + j4];
        #pragma unroll
        for (int m = 0; m < 4; m++) {
            float2 u0 = unpack2(acc[m][0]), u1 = unpack2(acc[m][1]);
            float2 u2 = unpack2(acc[m][2]), u3 = unpack2(acc[m][3]);
            #pragma unroll
            for (int par = 0; par < 2; par++) {
                int d = d0 + 2 * m + par;
                if (d < NN) {
                    float4 c = *(const float4*)&g_cnt[d * 4];
                    float4 o;
                    o.x = ((par ? u0.y : u0.x) + c.x * b0.x + c.y * b1.x + c.z * b2v.x) * c.w;
                    o.y = ((par ? u1.y : u1.x) + c.x * b0.y + c.y * b1.y + c.z * b2v.y) * c.w;
                    o.z = ((par ? u2.y : u2.x) + c.x * b0.z + c.y * b1.z + c.z * b2v.z) * c.w;
                    o.w = ((par ? u3.y : u3.x) + c.x * b0.w + c.y * b1.w + c.z * b2v.w) * c.w;
                    *(float4*)&g_agg[d * H + j4] = o;
                }
            }
        }
        __syncwarp();
    }
}

// gh = h @ W_hh^T + b_hh -> g_buf   (transposed weights, fused 3 output groups)
__global__ __launch_bounds__(256, 1)
void k_gh(const float* __restrict__ W_hh, const float* __restrict__ b_hh) {
    extern __shared__ float sm[];
    float* Wsm = sm;                   // 128 * WTR
    float* bs = Wsm + H * WTR;         // 384
    float* stg = bs + H3;              // 8 * 32*XST
    for (int i = threadIdx.x; i < H3 * H; i += blockDim.x) {
        int jj = i >> 7, k = i & 127;
        Wsm[k * WTR + jj] = W_hh[i];
    }
    for (int i = threadIdx.x; i < H3; i += blockDim.x) bs[i] = b_hh[i];
    __syncthreads();

    int warp = threadIdx.x >> 5, lane = threadIdx.x & 31;
    float* xs = stg + warp * 32 * XST;
    int j4 = lane * 4;
    for (int d0 = (blockIdx.x * 8 + warp) * 8; d0 < NN; d0 += gridDim.x * 64) {
        ull acc[3][4][4];
        #pragma unroll
        for (int p = 0; p < 3; p++)
            #pragma unroll
            for (int m = 0; m < 4; m++)
                #pragma unroll
                for (int o = 0; o < 4; o++) acc[p][m][o] = 0ull;
        for (int kc = 0; kc < H; kc += 32) {
            __syncwarp();
            #pragma unroll
            for (int n = 0; n < 8; n++) {
                int d = d0 + n;
                xs[lane * XST + n] = (d < NN) ? g_h[d * H + kc + lane] : 0.f;
            }
            __syncwarp();
            #pragma unroll 2
            for (int kk = 0; kk < 32; kk++) {
                const float* wrow = Wsm + (kc + kk) * WTR + j4;
                ull xp[4];
                #pragma unroll
                for (int m = 0; m < 4; m++) xp[m] = *(const ull*)(xs + kk * XST + 2 * m);
                #pragma unroll
                for (int p = 0; p < 3; p++) {
                    float4 w = *(const float4*)(wrow + p * H);
                    ull w0 = pack2(w.x, w.x), w1 = pack2(w.y, w.y);
                    ull w2 = pack2(w.z, w.z), w3 = pack2(w.w, w.w);
                    #pragma unroll
                    for (int m = 0; m < 4; m++) {
                        fma2(acc[p][m][0], w0, xp[m]);
                        fma2(acc[p][m][1], w1, xp[m]);
                        fma2(acc[p][m][2], w2, xp[m]);
                        fma2(acc[p][m][3], w3, xp[m]);
                    }
                }
            }
        }
        #pragma unroll
        for (int m = 0; m < 4; m++) {
            #pragma unroll
            for (int p = 0; p < 3; p++) {
                float2 u0 = unpack2(acc[p][m][0]), u1 = unpack2(acc[p][m][1]);
                float2 u2 = unpack2(acc[p][m][2]), u3 = unpack2(acc[p][m][3]);
                float bx = bs[p * H + j4], by = bs[p * H + j4 + 1];
                float bz = bs[p * H + j4 + 2], bw = bs[p * H + j4 + 3];
                #pragma unroll
                for (int par = 0; par < 2; par++) {
                    int d = d0 + 2 * m + par;
                    if (d < NN) {
                        float4 o;
                        o.x = (par ? u0.y : u0.x) + bx;
                        o.y = (par ? u1.y : u1.x) + by;
                        o.z = (par ? u2.y : u2.x) + bz;
                        o.w = (par ? u3.y : u3.x) + bw;
                        *(float4*)&g_buf[d * H3 + p * H + j4] = o;
                    }
                }
            }
        }
        __syncwarp();
    }
}

// gi = agg @ W_ih^T + b_ih, fused GRU combine (gh in g_buf)
__global__ __launch_bounds__(256, 1)
void k_gru(const float* __restrict__ W_ih, const float* __restrict__ b_ih) {
    extern __shared__ float sm[];
    float* Wsm = sm;                   // 128 * WTR
    float* bs = Wsm + H * WTR;
    float* stg = bs + H3;
    for (int i = threadIdx.x; i < H3 * H; i += blockDim.x) {
        int jj = i >> 7, k = i & 127;
        Wsm[k * WTR + jj] = W_ih[i];
    }
    for (int i = threadIdx.x; i < H3; i += blockDim.x) bs[i] = b_ih[i];
    __syncthreads();

    int warp = threadIdx.x >> 5, lane = threadIdx.x & 31;
    float* xs = stg + warp * 32 * XST;
    int j4 = lane * 4;
    for (int d0 = (blockIdx.x * 8 + warp) * 8; d0 < NN; d0 += gridDim.x * 64) {
        ull acc[3][4][4];
        #pragma unroll
        for (int p = 0; p < 3; p++)
            #pragma unroll
            for (int m = 0; m < 4; m++)
                #pragma unroll
                for (int o = 0; o < 4; o++) acc[p][m][o] = 0ull;
        for (int kc = 0; kc < H; kc += 32) {
            __syncwarp();
            #pragma unroll
            for (int n = 0; n < 8; n++) {
                int d = d0 + n;
                xs[lane * XST + n] = (d < NN) ? g_agg[d * H + kc + lane] : 0.f;
            }
            __syncwarp();
            #pragma unroll 2
            for (int kk = 0; kk < 32; kk++) {
                const float* wrow = Wsm + (kc + kk) * WTR + j4;
                ull xp[4];
                #pragma unroll
                for (int m = 0; m < 4; m++) xp[m] = *(const ull*)(xs + kk * XST + 2 * m);
                #pragma unroll
                for (int p = 0; p < 3; p++) {
                    float4 w = *(const float4*)(wrow + p * H);
                    ull w0 = pack2(w.x, w.x), w1 = pack2(w.y, w.y);
                    ull w2 = pack2(w.z, w.z), w3 = pack2(w.w, w.w);
                    #pragma unroll
                    for (int m = 0; m < 4; m++) {
                        fma2(acc[p][m][0], w0, xp[m]);
                        fma2(acc[p][m][1], w1, xp[m]);
                        fma2(acc[p][m][2], w2, xp[m]);
                        fma2(acc[p][m][3], w3, xp[m]);
                    }
                }
            }
        }
        float4 br = *(const float4*)&bs[j4];
        float4 bz = *(const float4*)&bs[H + j4];
        float4 bn = *(const float4*)&bs[2 * H + j4];
        #pragma unroll
        for (int m = 0; m < 4; m++) {
            float2 r0 = unpack2(acc[0][m][0]), r1 = unpack2(acc[0][m][1]);
            float2 r2 = unpack2(acc[0][m][2]), r3 = unpack2(acc[0][m][3]);
            float2 z0 = unpack2(acc[1][m][0]), z1 = unpack2(acc[1][m][1]);
            float2 z2 = unpack2(acc[1][m][2]), z3 = unpack2(acc[1][m][3]);
            float2 n0 = unpack2(acc[2][m][0]), n1 = unpack2(acc[2][m][1]);
            float2 n2 = unpack2(acc[2][m][2]), n3 = unpack2(acc[2][m][3]);
            #pragma unroll
            for (int par = 0; par < 2; par++) {
                int d = d0 + 2 * m + par;
                if (d < NN) {
                    float4 ghr = *(const float4*)&g_buf[d * H3 + j4];
                    float4 ghz = *(const float4*)&g_buf[d * H3 + H + j4];
                    float4 ghn = *(const float4*)&g_buf[d * H3 + 2 * H + j4];
                    float4 hold = *(const float4*)&g_h[d * H + j4];
                    float4 o;
                    {
                        float r = 1.f / (1.f + expf(-((par ? r0.y : r0.x) + br.x + ghr.x)));
                        float z = 1.f / (1.f + expf(-((par ? z0.y : z0.x) + bz.x + ghz.x)));
                        float nv = tanhf((par ? n0.y : n0.x) + bn.x + r * ghn.x);
                        o.x = (1.f - z) * nv + z * hold.x;
                    }
                    {
                        float r = 1.f / (1.f + expf(-((par ? r1.y : r1.x) + br.y + ghr.y)));
                        float z = 1.f / (1.f + expf(-((par ? z1.y : z1.x) + bz.y + ghz.y)));
                        float nv = tanhf((par ? n1.y : n1.x) + bn.y + r * ghn.y);
                        o.y = (1.f - z) * nv + z * hold.y;
                    }
                    {
                        float r = 1.f / (1.f + expf(-((par ? r2.y : r2.x) + br.z + ghr.z)));
                        float z = 1.f / (1.f + expf(-((par ? z2.y : z2.x) + bz.z + ghz.z)));
                        float nv = tanhf((par ? n2.y : n2.x) + bn.z + r * ghn.z);
                        o.z = (1.f - z) * nv + z * hold.z;
                    }
                    {
                        float r = 1.f / (1.f + expf(-((par ? r3.y : r3.x) + br.w + ghr.w)));
                        float z = 1.f / (1.f + expf(-((par ? z3.y : z3.x) + bz.w + ghz.w)));
                        float nv = tanhf((par ? n3.y : n3.x) + bn.w + r * ghn.w);
                        o.w = (1.f - z) * nv + z * hold.w;
                    }
                    *(float4*)&g_h[d * H + j4] = o;
                }
            }
        }
        __syncwarp();
    }
}

// logits = relu([h, h0] @ W1 + b1) @ W2 + b2
__global__ __launch_bounds__(256, 1)
void k_out(const float* __restrict__ W1, const float* __restrict__ b1,
           const float* __restrict__ W2, const float* __restrict__ b2,
           float* __restrict__ out) {
    extern __shared__ float sm[];
    float* Wsm = sm;                 // 256*128
    float* b1s = Wsm + 2 * H * H;    // 128
    float* W2s = b1s + H;            // 128
    float* stg = W2s + H;            // 8 * 32*XST
    for (int i = threadIdx.x; i < 2 * H * H; i += blockDim.x) Wsm[i] = W1[i];
    if (threadIdx.x < H) { b1s[threadIdx.x] = b1[threadIdx.x]; W2s[threadIdx.x] = W2[threadIdx.x]; }
    __syncthreads();
    float b2v = b2[0];

    int warp = threadIdx.x >> 5, lane = threadIdx.x & 31;
    float* xs = stg + warp * 32 * XST;
    int j4 = lane * 4;
    for (int d0 = (blockIdx.x * 8 + warp) * 8; d0 < NN; d0 += gridDim.x * 64) {
        ull acc[4][4];
        #pragma unroll
        for (int m = 0; m < 4; m++)
            #pragma unroll
            for (int o = 0; o < 4; o++) acc[m][o] = 0ull;
        for (int kc = 0; kc < 2 * H; kc += 32) {
            __syncwarp();
            #pragma unroll
            for (int n = 0; n < 8; n++) {
                int d = d0 + n;
                int k = kc + lane;
                float v = 0.f;
                if (d < NN) v = (k < H) ? g_h[d * H + k] : g_h0[d * H + k - H];
                xs[lane * XST + n] = v;
            }
            __syncwarp();
            #pragma unroll 4
            for (int kk = 0; kk < 32; kk++) {
                float4 w = *(const float4*)(Wsm + (kc + kk) * H + j4);
                ull w0 = pack2(w.x, w.x), w1 = pack2(w.y, w.y);
                ull w2 = pack2(w.z, w.z), w3 = pack2(w.w, w.w);
                #pragma unroll
                for (int m = 0; m < 4; m++) {
                    ull xp = *(const ull*)(xs + kk * XST + 2 * m);
                    fma2(acc[m][0], w0, xp);
                    fma2(acc[m][1], w1, xp);
                    fma2(acc[m][2], w2, xp);
                    fma2(acc[m][3], w3, xp);
                }
            }
        }
        float4 wv2 = *(const float4*)&W2s[j4];
        float4 bv = *(const float4*)&b1s[j4];
        float pn[8];
        #pragma unroll
        for (int m = 0; m < 4; m++) {
            float2 u0 = unpack2(acc[m][0]), u1 = unpack2(acc[m][1]);
            float2 u2 = unpack2(acc[m][2]), u3 = unpack2(acc[m][3]);
            pn[2 * m + 0] = fmaxf(u0.x + bv.x, 0.f) * wv2.x + fmaxf(u1.x + bv.y, 0.f) * wv2.y +
                            fmaxf(u2.x + bv.z, 0.f) * wv2.z + fmaxf(u3.x + bv.w, 0.f) * wv2.w;
            pn[2 * m + 1] = fmaxf(u0.y + bv.x, 0.f) * wv2.x + fmaxf(u1.y + bv.y, 0.f) * wv2.y +
                            fmaxf(u2.y + bv.z, 0.f) * wv2.z + fmaxf(u3.y + bv.w, 0.f) * wv2.w;
        }
        #pragma unroll
        for (int o = 16; o > 0; o >>= 1) {
            #pragma unroll
            for (int n = 0; n < 8; n++) pn[n] += __shfl_down_sync(0xffffffffu, pn[n], o);
        }
        if (lane == 0) {
            #pragma unroll
            for (int n = 0; n < 8; n++)
                if (d0 + n < NN) out[d0 + n] = pn[n] + b2v;
        }
        __syncwarp();
    }
}

// ---------------- launch ----------------
extern "C" void kernel_launch(void* const* d_in, const int* in_sizes, int n_in,
                              void* d_out, int out_size) {
    const int* xidx = (const int*)d_in[0];
    const float* sel = (const float*)d_in[1];
    const int* eidx = (const int*)d_in[2];
    const int* etype = (const int*)d_in[3];
    const int* epos = (const int*)d_in[4];
    const float* emb = (const float*)d_in[5];
    const float* pos_enc = (const float*)d_in[6];
    const float* Wg = (const float*)d_in[7];
    const float* bg = (const float*)d_in[8];
    const float* Wt = (const float*)d_in[9];
    const float* bt = (const float*)d_in[10];
    const float* W_ih = (const float*)d_in[11];
    const float* W_hh = (const float*)d_in[12];
    const float* b_ih = (const float*)d_in[13];
    const float* b_hh = (const float*)d_in[14];
    const float* W1 = (const float*)d_in[15];
    const float* b1 = (const float*)d_in[16];
    const float* W2 = (const float*)d_in[17];
    const float* b2 = (const float*)d_in[18];
    float* out = (float*)d_out;

    const int smem_gate = (PD * H + H + 8 * PD * XST) * 4;          // 53760
    const int smem_agg  = (H3 * H + H3 + 8 * 32 * XST) * 4;         // 208384
    const int smem_gh   = (H * WTR + H3 + 8 * 32 * XST) * 4;        // 210432
    const int smem_out  = (2 * H * H + 2 * H + 8 * 32 * XST) * 4;   // 142336

    static int attr_done = 0;
    if (!attr_done) {
        cudaFuncSetAttribute(k_gate, cudaFuncAttributeMaxDynamicSharedMemorySize, smem_gate);
        cudaFuncSetAttribute(k_agg, cudaFuncAttributeMaxDynamicSharedMemorySize, smem_agg);
        cudaFuncSetAttribute(k_gh,  cudaFuncAttributeMaxDynamicSharedMemorySize, smem_gh);
        cudaFuncSetAttribute(k_gru, cudaFuncAttributeMaxDynamicSharedMemorySize, smem_gh);
        cudaFuncSetAttribute(k_out, cudaFuncAttributeMaxDynamicSharedMemorySize, smem_out);
        attr_done = 1;
    }

    k_zero0<<<512, 256>>>();
    k_init<<<(NN * H + 255) / 256, 256>>>(xidx, sel, emb);
    k_histo<<<(NE + 255) / 256, 256>>>(eidx, etype);
    k_scan1<<<SCAN_NB, 256>>>();
    k_scan2<<<1, 32>>>();
    k_scan3<<<SCAN_NB, SCAN_B>>>();
    k_fill<<<(NE + 255) / 256, 256>>>(eidx, etype);
    k_denom<<<(NN + 255) / 256, 256>>>();
    k_gate<<<592, 256, smem_gate>>>(epos, pos_enc, Wg, bg);

    for (int it = 0; it < GITERS; it++) {
        k_gather<<<2048, 256>>>();
        k_agg<<<148, 256, smem_agg>>>(Wt, bt);
        k_gh<<<148, 256, smem_gh>>>(W_hh, b_hh);
        k_gru<<<148, 256, smem_gh>>>(W_ih, b_ih);
    }

    k_out<<<148, 256, smem_out>>>(W1, b1, W2, b2, out);
}

// round 17
// speedup vs baseline: 2.3130x; 1.1487x over previous
#include <cuda_runtime.h>
#include <math.h>

#define NN 100000
#define NE 640000
#define H 128
#define H3 384
#define TT 3
#define PD 64
#define EMBD 96
#define SELD 32
#define GITERS 6
#define WTR 388   // transposed-weight row stride (floats): 16B-aligned, conflict-free
#define XST 10    // x staging stride (floats): 8B-aligned pairs, <=2-way STS conflict

typedef unsigned long long ull;

// ---------------- f32x2 helpers ----------------
__device__ __forceinline__ void fma2(ull& d, ull a, ull b) {
    asm("fma.rn.f32x2 %0, %1, %2, %0;" : "+l"(d) : "l"(a), "l"(b));
}
__device__ __forceinline__ ull pack2(float lo, float hi) {
    ull r; asm("mov.b64 %0, {%1, %2};" : "=l"(r) : "f"(lo), "f"(hi)); return r;
}
__device__ __forceinline__ float2 unpack2(ull v) {
    float2 r; asm("mov.b64 {%0, %1}, %2;" : "=f"(r.x), "=f"(r.y) : "l"(v)); return r;
}

// ---------------- static device scratch ----------------
__device__ float g_h[NN * H];
__device__ float g_h0[NN * H];
__device__ float g_agg[NN * H];
__device__ float g_buf[NN * H3];    // msg sums, then reused as gh scratch
__device__ float g_gate[NE * H];    // gate in CSR-sorted edge order
__device__ float g_cnt[NN * 4];     // per-type in-counts + 1/max(total,1)
__device__ int   g_deg[NN];
__device__ int   g_cur[NN];
__device__ int   g_off[NN + 1];
__device__ int   g_srcs[NE];
__device__ int   g_types[NE];
__device__ int   g_eperm[NE];
__device__ int   g_bsum[128];
__device__ int   g_bpre[128];

#define SCAN_B 1024
#define SCAN_NB 98   // ceil(100000/1024)

// ---------------- setup ----------------
__global__ void k_zero0() {
    int stride = gridDim.x * blockDim.x;
    int tid = blockIdx.x * blockDim.x + threadIdx.x;
    for (int i = tid; i < NN; i += stride) { g_deg[i] = 0; g_cur[i] = 0; }
    for (int i = tid; i < NN * 4; i += stride) g_cnt[i] = 0.f;
}

__global__ void k_init(const int* __restrict__ xidx, const float* __restrict__ sel,
                       const float* __restrict__ emb) {
    int i = blockIdx.x * blockDim.x + threadIdx.x;
    if (i >= NN * H) return;
    int node = i >> 7, d = i & 127;
    float v = (d < EMBD) ? emb[xidx[node] * EMBD + d] : sel[node * SELD + d - EMBD];
    g_h0[i] = v;
    g_h[i] = v;
}

__global__ void k_histo(const int* __restrict__ eidx, const int* __restrict__ etype) {
    int e = blockIdx.x * blockDim.x + threadIdx.x;
    if (e < NE) {
        int dst = eidx[NE + e];
        atomicAdd(&g_deg[dst], 1);
        atomicAdd(&g_cnt[dst * 4 + etype[e]], 1.f);
    }
}

// coalesced 3-phase scan of g_deg -> g_off
__global__ void k_scan1() {
    __shared__ int wsum[8];
    int base = blockIdx.x * SCAN_B;
    int s = 0;
    for (int i = threadIdx.x; i < SCAN_B; i += blockDim.x) {
        int idx = base + i;
        s += (idx < NN) ? g_deg[idx] : 0;
    }
    for (int o = 16; o > 0; o >>= 1) s += __shfl_down_sync(0xffffffffu, s, o);
    int lane = threadIdx.x & 31, wid = threadIdx.x >> 5;
    if (lane == 0) wsum[wid] = s;
    __syncthreads();
    if (threadIdx.x == 0) {
        int t = 0;
        for (int w = 0; w < (int)(blockDim.x >> 5); w++) t += wsum[w];
        g_bsum[blockIdx.x] = t;
    }
}
__global__ void k_scan2() {
    if (threadIdx.x == 0) {
        int run = 0;
        for (int b = 0; b < SCAN_NB; b++) { g_bpre[b] = run; run += g_bsum[b]; }
        g_off[NN] = NE;
    }
}
__global__ void k_scan3() {
    __shared__ int wsum[32];
    int i = blockIdx.x * SCAN_B + threadIdx.x;
    int lane = threadIdx.x & 31, wid = threadIdx.x >> 5;
    int x = (i < NN) ? g_deg[i] : 0;
    int incl = x;
    for (int o = 1; o < 32; o <<= 1) {
        int v = __shfl_up_sync(0xffffffffu, incl, o);
        if (lane >= o) incl += v;
    }
    if (lane == 31) wsum[wid] = incl;
    __syncthreads();
    if (wid == 0) {
        int s = wsum[lane];
        for (int o = 1; o < 32; o <<= 1) {
            int v = __shfl_up_sync(0xffffffffu, s, o);
            if (lane >= o) s += v;
        }
        wsum[lane] = s;
    }
    __syncthreads();
    int excl = incl - x + (wid > 0 ? wsum[wid - 1] : 0);
    if (i < NN) g_off[i] = g_bpre[blockIdx.x] + excl;
}

__global__ void k_fill(const int* __restrict__ eidx, const int* __restrict__ etype) {
    int e = blockIdx.x * blockDim.x + threadIdx.x;
    if (e < NE) {
        int dst = eidx[NE + e];
        int p = g_off[dst] + atomicAdd(&g_cur[dst], 1);
        g_srcs[p] = eidx[e];
        g_types[p] = etype[e];
        g_eperm[p] = e;
    }
}

__global__ void k_denom() {
    int n = blockIdx.x * blockDim.x + threadIdx.x;
    if (n < NN) {
        float c = g_cnt[n * 4] + g_cnt[n * 4 + 1] + g_cnt[n * 4 + 2];
        g_cnt[n * 4 + 3] = 1.f / fmaxf(c, 1.f);
    }
}

// gate[p][:] = 2*sigmoid(pos_enc[pos[eperm[p]]] @ Wg + bg)  — f32x2 node-pair GEMM
__global__ __launch_bounds__(256, 1)
void k_gate(const int* __restrict__ epos, const float* __restrict__ pos_enc,
            const float* __restrict__ Wg, const float* __restrict__ bg) {
    extern __shared__ float sm[];
    float* Wsm = sm;                // PD*H = 8192
    float* bgs = Wsm + PD * H;      // 128
    float* stg = bgs + H;           // 8 warps * 64*XST
    for (int i = threadIdx.x; i < PD * H; i += blockDim.x) Wsm[i] = Wg[i];
    if (threadIdx.x < H) bgs[threadIdx.x] = bg[threadIdx.x];
    __syncthreads();

    int warp = threadIdx.x >> 5, lane = threadIdx.x & 31;
    float* xs = stg + warp * PD * XST;
    int j4 = lane * 4;
    for (int e0 = (blockIdx.x * 8 + warp) * 8; e0 < NE; e0 += gridDim.x * 64) {
        __syncwarp();
        #pragma unroll
        for (int it = 0; it < 16; it++) {
            int idx = it * 32 + lane;
            int n = idx >> 6, kk = idx & 63;
            int p = e0 + n;
            xs[kk * XST + n] = (p < NE) ? pos_enc[epos[g_eperm[p]] * PD + kk] : 0.f;
        }
        __syncwarp();
        ull acc[4][4];
        #pragma unroll
        for (int m = 0; m < 4; m++)
            #pragma unroll
            for (int o = 0; o < 4; o++) acc[m][o] = 0ull;
        #pragma unroll 4
        for (int kk = 0; kk < PD; kk++) {
            float4 w = *(const float4*)(Wsm + kk * H + j4);
            ull w0 = pack2(w.x, w.x), w1 = pack2(w.y, w.y);
            ull w2 = pack2(w.z, w.z), w3 = pack2(w.w, w.w);
            #pragma unroll
            for (int m = 0; m < 4; m++) {
                ull xp = *(const ull*)(xs + kk * XST + 2 * m);
                fma2(acc[m][0], w0, xp);
                fma2(acc[m][1], w1, xp);
                fma2(acc[m][2], w2, xp);
                fma2(acc[m][3], w3, xp);
            }
        }
        float4 bv = *(const float4*)&bgs[j4];
        #pragma unroll
        for (int m = 0; m < 4; m++) {
            float2 u0 = unpack2(acc[m][0]), u1 = unpack2(acc[m][1]);
            float2 u2 = unpack2(acc[m][2]), u3 = unpack2(acc[m][3]);
            #pragma unroll
            for (int par = 0; par < 2; par++) {
                int e = e0 + 2 * m + par;
                if (e < NE) {
                    float4 o;
                    o.x = 2.f / (1.f + expf(-((par ? u0.y : u0.x) + bv.x)));
                    o.y = 2.f / (1.f + expf(-((par ? u1.y : u1.x) + bv.y)));
                    o.z = 2.f / (1.f + expf(-((par ? u2.y : u2.x) + bv.z)));
                    o.w = 2.f / (1.f + expf(-((par ? u3.y : u3.x) + bv.w)));
                    *(float4*)&g_gate[e * H + j4] = o;
                }
            }
        }
        __syncwarp();
    }
}

// ---------------- per-iteration ----------------
__global__ void k_gather() {
    int gwarp = (blockIdx.x * blockDim.x + threadIdx.x) >> 5;
    int lane = threadIdx.x & 31;
    int nwarps = (gridDim.x * blockDim.x) >> 5;
    int j = lane * 4;
    for (int n = gwarp; n < NN; n += nwarps) {
        int p0 = g_off[n], p1 = g_off[n + 1];
        float4 a0 = {0, 0, 0, 0}, a1 = {0, 0, 0, 0}, a2 = {0, 0, 0, 0};
        for (int p = p0; p < p1; p++) {
            int src = __ldg(&g_srcs[p]);
            int t = __ldg(&g_types[p]);
            float4 hv = *(const float4*)&g_h[src * H + j];
            float4 gv = *(const float4*)&g_gate[p * H + j];
            if (t == 0) {
                a0.x += hv.x * gv.x; a0.y += hv.y * gv.y; a0.z += hv.z * gv.z; a0.w += hv.w * gv.w;
            } else if (t == 1) {
                a1.x += hv.x * gv.x; a1.y += hv.y * gv.y; a1.z += hv.z * gv.z; a1.w += hv.w * gv.w;
            } else {
                a2.x += hv.x * gv.x; a2.y += hv.y * gv.y; a2.z += hv.z * gv.z; a2.w += hv.w * gv.w;
            }
        }
        *(float4*)&g_buf[n * H3 + 0 * H + j] = a0;
        *(float4*)&g_buf[n * H3 + 1 * H + j] = a1;
        *(float4*)&g_buf[n * H3 + 2 * H + j] = a2;
    }
}

// agg[d][:] = inv * ( sum_tk buf[d][tk] * Wt[tk][:] + sum_t cnt_t*bt[t][:] )
// x staging double-buffered: prefetch next chunk to regs during compute
__global__ __launch_bounds__(256, 1)
void k_agg(const float* __restrict__ Wt, const float* __restrict__ bt) {
    extern __shared__ float sm[];
    float* Wsm = sm;                   // 384*128
    float* bts = Wsm + H3 * H;         // 384
    float* stg = bts + H3;             // 8 * 32*XST
    for (int i = threadIdx.x; i < H3 * H; i += blockDim.x) Wsm[i] = Wt[i];
    for (int i = threadIdx.x; i < H3; i += blockDim.x) bts[i] = bt[i];
    __syncthreads();

    int warp = threadIdx.x >> 5, lane = threadIdx.x & 31;
    float* xs = stg + warp * 32 * XST;
    int j4 = lane * 4;
    for (int d0 = (blockIdx.x * 8 + warp) * 8; d0 < NN; d0 += gridDim.x * 64) {
        ull acc[4][4];
        #pragma unroll
        for (int m = 0; m < 4; m++)
            #pragma unroll
            for (int o = 0; o < 4; o++) acc[m][o] = 0ull;
        float xr[8];
        #pragma unroll
        for (int n = 0; n < 8; n++) {
            int d = d0 + n;
            xr[n] = (d < NN) ? g_buf[d * H3 + lane] : 0.f;
        }
        for (int kc = 0; kc < H3; kc += 32) {
            __syncwarp();
            #pragma unroll
            for (int n = 0; n < 8; n++) xs[lane * XST + n] = xr[n];
            __syncwarp();
            if (kc + 32 < H3) {
                #pragma unroll
                for (int n = 0; n < 8; n++) {
                    int d = d0 + n;
                    xr[n] = (d < NN) ? g_buf[d * H3 + kc + 32 + lane] : 0.f;
                }
            }
            #pragma unroll 4
            for (int kk = 0; kk < 32; kk++) {
                float4 w = *(const float4*)(Wsm + (kc + kk) * H + j4);
                ull w0 = pack2(w.x, w.x), w1 = pack2(w.y, w.y);
                ull w2 = pack2(w.z, w.z), w3 = pack2(w.w, w.w);
                #pragma unroll
                for (int m = 0; m < 4; m++) {
                    ull xp = *(const ull*)(xs + kk * XST + 2 * m);
                    fma2(acc[m][0], w0, xp);
                    fma2(acc[m][1], w1, xp);
                    fma2(acc[m][2], w2, xp);
                    fma2(acc[m][3], w3, xp);
                }
            }
        }
        float4 b0 = *(const float4*)&bts[j4];
        float4 b1 = *(const float4*)&bts[H + j4];
        float4 b2v = *(const float4*)&bts[2 * H + j4];
        #pragma unroll
        for (int m = 0; m < 4; m++) {
            float2 u0 = unpack2(acc[m][0]), u1 = unpack2(acc[m][1]);
            float2 u2 = unpack2(acc[m][2]), u3 = unpack2(acc[m][3]);
            #pragma unroll
            for (int par = 0; par < 2; par++) {
                int d = d0 + 2 * m + par;
                if (d < NN) {
                    float4 c = *(const float4*)&g_cnt[d * 4];
                    float4 o;
                    o.x = ((par ? u0.y : u0.x) + c.x * b0.x + c.y * b1.x + c.z * b2v.x) * c.w;
                    o.y = ((par ? u1.y : u1.x) + c.x * b0.y + c.y * b1.y + c.z * b2v.y) * c.w;
                    o.z = ((par ? u2.y : u2.x) + c.x * b0.z + c.y * b1.z + c.z * b2v.z) * c.w;
                    o.w = ((par ? u3.y : u3.x) + c.x * b0.w + c.y * b1.w + c.z * b2v.w) * c.w;
                    *(float4*)&g_agg[d * H + j4] = o;
                }
            }
        }
        __syncwarp();
    }
}

// gh = h @ W_hh^T + b_hh -> g_buf   (transposed weights, fused 3 output groups, prefetched x)
__global__ __launch_bounds__(256, 1)
void k_gh(const float* __restrict__ W_hh, const float* __restrict__ b_hh) {
    extern __shared__ float sm[];
    float* Wsm = sm;                   // 128 * WTR
    float* bs = Wsm + H * WTR;         // 384
    float* stg = bs + H3;              // 8 * 32*XST
    for (int i = threadIdx.x; i < H3 * H; i += blockDim.x) {
        int jj = i >> 7, k = i & 127;
        Wsm[k * WTR + jj] = W_hh[i];
    }
    for (int i = threadIdx.x; i < H3; i += blockDim.x) bs[i] = b_hh[i];
    __syncthreads();

    int warp = threadIdx.x >> 5, lane = threadIdx.x & 31;
    float* xs = stg + warp * 32 * XST;
    int j4 = lane * 4;
    for (int d0 = (blockIdx.x * 8 + warp) * 8; d0 < NN; d0 += gridDim.x * 64) {
        ull acc[3][4][4];
        #pragma unroll
        for (int p = 0; p < 3; p++)
            #pragma unroll
            for (int m = 0; m < 4; m++)
                #pragma unroll
                for (int o = 0; o < 4; o++) acc[p][m][o] = 0ull;
        float xr[8];
        #pragma unroll
        for (int n = 0; n < 8; n++) {
            int d = d0 + n;
            xr[n] = (d < NN) ? g_h[d * H + lane] : 0.f;
        }
        for (int kc = 0; kc < H; kc += 32) {
            __syncwarp();
            #pragma unroll
            for (int n = 0; n < 8; n++) xs[lane * XST + n] = xr[n];
            __syncwarp();
            if (kc + 32 < H) {
                #pragma unroll
                for (int n = 0; n < 8; n++) {
                    int d = d0 + n;
                    xr[n] = (d < NN) ? g_h[d * H + kc + 32 + lane] : 0.f;
                }
            }
            #pragma unroll 2
            for (int kk = 0; kk < 32; kk++) {
                const float* wrow = Wsm + (kc + kk) * WTR + j4;
                ull xp[4];
                #pragma unroll
                for (int m = 0; m < 4; m++) xp[m] = *(const ull*)(xs + kk * XST + 2 * m);
                #pragma unroll
                for (int p = 0; p < 3; p++) {
                    float4 w = *(const float4*)(wrow + p * H);
                    ull w0 = pack2(w.x, w.x), w1 = pack2(w.y, w.y);
                    ull w2 = pack2(w.z, w.z), w3 = pack2(w.w, w.w);
                    #pragma unroll
                    for (int m = 0; m < 4; m++) {
                        fma2(acc[p][m][0], w0, xp[m]);
                        fma2(acc[p][m][1], w1, xp[m]);
                        fma2(acc[p][m][2], w2, xp[m]);
                        fma2(acc[p][m][3], w3, xp[m]);
                    }
                }
            }
        }
        #pragma unroll
        for (int m = 0; m < 4; m++) {
            #pragma unroll
            for (int p = 0; p < 3; p++) {
                float2 u0 = unpack2(acc[p][m][0]), u1 = unpack2(acc[p][m][1]);
                float2 u2 = unpack2(acc[p][m][2]), u3 = unpack2(acc[p][m][3]);
                float bx = bs[p * H + j4], by = bs[p * H + j4 + 1];
                float bz = bs[p * H + j4 + 2], bw = bs[p * H + j4 + 3];
                #pragma unroll
                for (int par = 0; par < 2; par++) {
                    int d = d0 + 2 * m + par;
                    if (d < NN) {
                        float4 o;
                        o.x = (par ? u0.y : u0.x) + bx;
                        o.y = (par ? u1.y : u1.x) + by;
                        o.z = (par ? u2.y : u2.x) + bz;
                        o.w = (par ? u3.y : u3.x) + bw;
                        *(float4*)&g_buf[d * H3 + p * H + j4] = o;
                    }
                }
            }
        }
        __syncwarp();
    }
}

// gi = agg @ W_ih^T + b_ih, fused GRU combine (gh in g_buf), prefetched x
__global__ __launch_bounds__(256, 1)
void k_gru(const float* __restrict__ W_ih, const float* __restrict__ b_ih) {
    extern __shared__ float sm[];
    float* Wsm = sm;                   // 128 * WTR
    float* bs = Wsm + H * WTR;
    float* stg = bs + H3;
    for (int i = threadIdx.x; i < H3 * H; i += blockDim.x) {
        int jj = i >> 7, k = i & 127;
        Wsm[k * WTR + jj] = W_ih[i];
    }
    for (int i = threadIdx.x; i < H3; i += blockDim.x) bs[i] = b_ih[i];
    __syncthreads();

    int warp = threadIdx.x >> 5, lane = threadIdx.x & 31;
    float* xs = stg + warp * 32 * XST;
    int j4 = lane * 4;
    for (int d0 = (blockIdx.x * 8 + warp) * 8; d0 < NN; d0 += gridDim.x * 64) {
        ull acc[3][4][4];
        #pragma unroll
        for (int p = 0; p < 3; p++)
            #pragma unroll
            for (int m = 0; m < 4; m++)
                #pragma unroll
                for (int o = 0; o < 4; o++) acc[p][m][o] = 0ull;
        float xr[8];
        #pragma unroll
        for (int n = 0; n < 8; n++) {
            int d = d0 + n;
            xr[n] = (d < NN) ? g_agg[d * H + lane] : 0.f;
        }
        for (int kc = 0; kc < H; kc += 32) {
            __syncwarp();
            #pragma unroll
            for (int n = 0; n < 8; n++) xs[lane * XST + n] = xr[n];
            __syncwarp();
            if (kc + 32 < H) {
                #pragma unroll
                for (int n = 0; n < 8; n++) {
                    int d = d0 + n;
                    xr[n] = (d < NN) ? g_agg[d * H + kc + 32 + lane] : 0.f;
                }
            }
            #pragma unroll 2
            for (int kk = 0; kk < 32; kk++) {
                const float* wrow = Wsm + (kc + kk) * WTR + j4;
                ull xp[4];
                #pragma unroll
                for (int m = 0; m < 4; m++) xp[m] = *(const ull*)(xs + kk * XST + 2 * m);
                #pragma unroll
                for (int p = 0; p < 3; p++) {
                    float4 w = *(const float4*)(wrow + p * H);
                    ull w0 = pack2(w.x, w.x), w1 = pack2(w.y, w.y);
                    ull w2 = pack2(w.z, w.z), w3 = pack2(w.w, w.w);
                    #pragma unroll
                    for (int m = 0; m < 4; m++) {
                        fma2(acc[p][m][0], w0, xp[m]);
                        fma2(acc[p][m][1], w1, xp[m]);
                        fma2(acc[p][m][2], w2, xp[m]);
                        fma2(acc[p][m][3], w3, xp[m]);
                    }
                }
            }
        }
        float4 br = *(const float4*)&bs[j4];
        float4 bz = *(const float4*)&bs[H + j4];
        float4 bn = *(const float4*)&bs[2 * H + j4];
        #pragma unroll
        for (int m = 0; m < 4; m++) {
            float2 r0 = unpack2(acc[0][m][0]), r1 = unpack2(acc[0][m][1]);
            float2 r2 = unpack2(acc[0][m][2]), r3 = unpack2(acc[0][m][3]);
            float2 z0 = unpack2(acc[1][m][0]), z1 = unpack2(acc[1][m][1]);
            float2 z2 = unpack2(acc[1][m][2]), z3 = unpack2(acc[1][m][3]);
            float2 n0 = unpack2(acc[2][m][0]), n1 = unpack2(acc[2][m][1]);
            float2 n2 = unpack2(acc[2][m][2]), n3 = unpack2(acc[2][m][3]);
            #pragma unroll
            for (int par = 0; par < 2; par++) {
                int d = d0 + 2 * m + par;
                if (d < NN) {
                    float4 ghr = *(const float4*)&g_buf[d * H3 + j4];
                    float4 ghz = *(const float4*)&g_buf[d * H3 + H + j4];
                    float4 ghn = *(const float4*)&g_buf[d * H3 + 2 * H + j4];
                    float4 hold = *(const float4*)&g_h[d * H + j4];
                    float4 o;
                    {
                        float r = 1.f / (1.f + expf(-((par ? r0.y : r0.x) + br.x + ghr.x)));
                        float z = 1.f / (1.f + expf(-((par ? z0.y : z0.x) + bz.x + ghz.x)));
                        float nv = tanhf((par ? n0.y : n0.x) + bn.x + r * ghn.x);
                        o.x = (1.f - z) * nv + z * hold.x;
                    }
                    {
                        float r = 1.f / (1.f + expf(-((par ? r1.y : r1.x) + br.y + ghr.y)));
                        float z = 1.f / (1.f + expf(-((par ? z1.y : z1.x) + bz.y + ghz.y)));
                        float nv = tanhf((par ? n1.y : n1.x) + bn.y + r * ghn.y);
                        o.y = (1.f - z) * nv + z * hold.y;
                    }
                    {
                        float r = 1.f / (1.f + expf(-((par ? r2.y : r2.x) + br.z + ghr.z)));
                        float z = 1.f / (1.f + expf(-((par ? z2.y : z2.x) + bz.z + ghz.z)));
                        float nv = tanhf((par ? n2.y : n2.x) + bn.z + r * ghn.z);
                        o.z = (1.f - z) * nv + z * hold.z;
                    }
                    {
                        float r = 1.f / (1.f + expf(-((par ? r3.y : r3.x) + br.w + ghr.w)));
                        float z = 1.f / (1.f + expf(-((par ? z3.y : z3.x) + bz.w + ghz.w)));
                        float nv = tanhf((par ? n3.y : n3.x) + bn.w + r * ghn.w);
                        o.w = (1.f - z) * nv + z * hold.w;
                    }
                    *(float4*)&g_h[d * H + j4] = o;
                }
            }
        }
        __syncwarp();
    }
}

// logits = relu([h, h0] @ W1 + b1) @ W2 + b2   (prefetched x)
__global__ __launch_bounds__(256, 1)
void k_out(const float* __restrict__ W1, const float* __restrict__ b1,
           const float* __restrict__ W2, const float* __restrict__ b2,
           float* __restrict__ out) {
    extern __shared__ float sm[];
    float* Wsm = sm;                 // 256*128
    float* b1s = Wsm + 2 * H * H;    // 128
    float* W2s = b1s + H;            // 128
    float* stg = W2s + H;            // 8 * 32*XST
    for (int i = threadIdx.x; i < 2 * H * H; i += blockDim.x) Wsm[i] = W1[i];
    if (threadIdx.x < H) { b1s[threadIdx.x] = b1[threadIdx.x]; W2s[threadIdx.x] = W2[threadIdx.x]; }
    __syncthreads();
    float b2v = b2[0];

    int warp = threadIdx.x >> 5, lane = threadIdx.x & 31;
    float* xs = stg + warp * 32 * XST;
    int j4 = lane * 4;
    for (int d0 = (blockIdx.x * 8 + warp) * 8; d0 < NN; d0 += gridDim.x * 64) {
        ull acc[4][4];
        #pragma unroll
        for (int m = 0; m < 4; m++)
            #pragma unroll
            for (int o = 0; o < 4; o++) acc[m][o] = 0ull;
        float xr[8];
        #pragma unroll
        for (int n = 0; n < 8; n++) {
            int d = d0 + n;
            xr[n] = (d < NN) ? g_h[d * H + lane] : 0.f;
        }
        for (int kc = 0; kc < 2 * H; kc += 32) {
            __syncwarp();
            #pragma unroll
            for (int n = 0; n < 8; n++) xs[lane * XST + n] = xr[n];
            __syncwarp();
            if (kc + 32 < 2 * H) {
                int k = kc + 32 + lane;
                #pragma unroll
                for (int n = 0; n < 8; n++) {
                    int d = d0 + n;
                    float v = 0.f;
                    if (d < NN) v = (k < H) ? g_h[d * H + k] : g_h0[d * H + k - H];
                    xr[n] = v;
                }
            }
            #pragma unroll 4
            for (int kk = 0; kk < 32; kk++) {
                float4 w = *(const float4*)(Wsm + (kc + kk) * H + j4);
                ull w0 = pack2(w.x, w.x), w1 = pack2(w.y, w.y);
                ull w2 = pack2(w.z, w.z), w3 = pack2(w.w, w.w);
                #pragma unroll
                for (int m = 0; m < 4; m++) {
                    ull xp = *(const ull*)(xs + kk * XST + 2 * m);
                    fma2(acc[m][0], w0, xp);
                    fma2(acc[m][1], w1, xp);
                    fma2(acc[m][2], w2, xp);
                    fma2(acc[m][3], w3, xp);
                }
            }
        }
        float4 wv2 = *(const float4*)&W2s[j4];
        float4 bv = *(const float4*)&b1s[j4];
        float pn[8];
        #pragma unroll
        for (int m = 0; m < 4; m++) {
            float2 u0 = unpack2(acc[m][0]), u1 = unpack2(acc[m][1]);
            float2 u2 = unpack2(acc[m][2]), u3 = unpack2(acc[m][3]);
            pn[2 * m + 0] = fmaxf(u0.x + bv.x, 0.f) * wv2.x + fmaxf(u1.x + bv.y, 0.f) * wv2.y +
                            fmaxf(u2.x + bv.z, 0.f) * wv2.z + fmaxf(u3.x + bv.w, 0.f) * wv2.w;
            pn[2 * m + 1] = fmaxf(u0.y + bv.x, 0.f) * wv2.x + fmaxf(u1.y + bv.y, 0.f) * wv2.y +
                            fmaxf(u2.y + bv.z, 0.f) * wv2.z + fmaxf(u3.y + bv.w, 0.f) * wv2.w;
        }
        #pragma unroll
        for (int o = 16; o > 0; o >>= 1) {
            #pragma unroll
            for (int n = 0; n < 8; n++) pn[n] += __shfl_down_sync(0xffffffffu, pn[n], o);
        }
        if (lane == 0) {
            #pragma unroll
            for (int n = 0; n < 8; n++)
                if (d0 + n < NN) out[d0 + n] = pn[n] + b2v;
        }
        __syncwarp();
    }
}

// ---------------- launch ----------------
extern "C" void kernel_launch(void* const* d_in, const int* in_sizes, int n_in,
                              void* d_out, int out_size) {
    const int* xidx = (const int*)d_in[0];
    const float* sel = (const float*)d_in[1];
    const int* eidx = (const int*)d_in[2];
    const int* etype = (const int*)d_in[3];
    const int* epos = (const int*)d_in[4];
    const float* emb = (const float*)d_in[5];
    const float* pos_enc = (const float*)d_in[6];
    const float* Wg = (const float*)d_in[7];
    const float* bg = (const float*)d_in[8];
    const float* Wt = (const float*)d_in[9];
    const float* bt = (const float*)d_in[10];
    const float* W_ih = (const float*)d_in[11];
    const float* W_hh = (const float*)d_in[12];
    const float* b_ih = (const float*)d_in[13];
    const float* b_hh = (const float*)d_in[14];
    const float* W1 = (const float*)d_in[15];
    const float* b1 = (const float*)d_in[16];
    const float* W2 = (const float*)d_in[17];
    const float* b2 = (const float*)d_in[18];
    float* out = (float*)d_out;

    const int smem_gate = (PD * H + H + 8 * PD * XST) * 4;          // 53760
    const int smem_agg  = (H3 * H + H3 + 8 * 32 * XST) * 4;         // 208384
    const int smem_gh   = (H * WTR + H3 + 8 * 32 * XST) * 4;        // 210432
    const int smem_out  = (2 * H * H + 2 * H + 8 * 32 * XST) * 4;   // 142336

    static int attr_done = 0;
    if (!attr_done) {
        cudaFuncSetAttribute(k_gate, cudaFuncAttributeMaxDynamicSharedMemorySize, smem_gate);
        cudaFuncSetAttribute(k_agg, cudaFuncAttributeMaxDynamicSharedMemorySize, smem_agg);
        cudaFuncSetAttribute(k_gh,  cudaFuncAttributeMaxDynamicSharedMemorySize, smem_gh);
        cudaFuncSetAttribute(k_gru, cudaFuncAttributeMaxDynamicSharedMemorySize, smem_gh);
        cudaFuncSetAttribute(k_out, cudaFuncAttributeMaxDynamicSharedMemorySize, smem_out);
        attr_done = 1;
    }

    k_zero0<<<512, 256>>>();
    k_init<<<(NN * H + 255) / 256, 256>>>(xidx, sel, emb);
    k_histo<<<(NE + 255) / 256, 256>>>(eidx, etype);
    k_scan1<<<SCAN_NB, 256>>>();
    k_scan2<<<1, 32>>>();
    k_scan3<<<SCAN_NB, SCAN_B>>>();
    k_fill<<<(NE + 255) / 256, 256>>>(eidx, etype);
    k_denom<<<(NN + 255) / 256, 256>>>();
    k_gate<<<592, 256, smem_gate>>>(epos, pos_enc, Wg, bg);

    for (int it = 0; it < GITERS; it++) {
        k_gather<<<2048, 256>>>();
        k_agg<<<148, 256, smem_agg>>>(Wt, bt);
        k_gh<<<148, 256, smem_gh>>>(W_hh, b_hh);
        k_gru<<<148, 256, smem_gh>>>(W_ih, b_ih);
    }

    k_out<<<148, 256, smem_out>>>(W1, b1, W2, b2, out);
}